// round 2
// baseline (speedup 1.0000x reference)
#include <cuda_runtime.h>
#include <cstdint>

#define Bq 32
#define Sq 256
#define Eq 256
#define Hq 512
#define Gq 2048          // 4*H
#define NCq 4
#define M_TOT (Bq * Sq)  // 8192

#define SCAN_NCTA 128
#define SCAN_TPB  256
#define HPAD      516
#define SCAN_SMEM_FLOATS (16 * Hq + Bq * HPAD + 16 * 33 + 128)
#define SCAN_SMEM_BYTES  (SCAN_SMEM_FLOATS * 4)

// ---------------- device scratch (static, no allocation) ----------------
__device__ float g_gx[M_TOT * Gq];     // 64MB gate pre-activations; reused as probs
__device__ float g_io0[M_TOT * Hq];    // 16MB layer ping
__device__ float g_io1[M_TOT * Hq];    // 16MB layer pong
__device__ float g_hbuf[2][Hq * Bq];   // recurrent h double buffer, layout [k][b]
__device__ unsigned g_bar_count = 0;
__device__ unsigned g_bar_gen   = 0;

// ---------------- software grid barrier (all CTAs co-resident) ----------
__device__ __forceinline__ void grid_barrier() {
    __syncthreads();
    if (threadIdx.x == 0) {
        __threadfence();
        unsigned gen = atomicAdd(&g_bar_gen, 0u);
        if (atomicAdd(&g_bar_count, 1u) == gridDim.x - 1) {
            atomicExch(&g_bar_count, 0u);
            __threadfence();
            atomicAdd(&g_bar_gen, 1u);
        } else {
            while (atomicAdd(&g_bar_gen, 0u) == gen) { __nanosleep(32); }
        }
        __threadfence();
    }
    __syncthreads();
}

// ---------------- input GEMM: C[m][g] = A[m][:]·W[g][:] + bih[g]+bhh[g] --
// A: [8192][K] row-major, W: [2048][K] row-major, C: [8192][2048]
__global__ void __launch_bounds__(256) gemm_kernel(
    const float* __restrict__ A, const float* __restrict__ W,
    const float* __restrict__ bih, const float* __restrict__ bhh,
    float* __restrict__ C, int K)
{
    __shared__ float As[8][128];
    __shared__ float Bs[8][128];
    const int tid = threadIdx.x;
    const int m0 = blockIdx.y * 128;
    const int n0 = blockIdx.x * 128;
    const int lr = tid >> 1;
    const int lk = (tid & 1) * 4;
    const int tx = tid & 15;
    const int ty = tid >> 4;

    float acc[8][8];
#pragma unroll
    for (int i = 0; i < 8; ++i)
#pragma unroll
        for (int j = 0; j < 8; ++j) acc[i][j] = 0.f;

    const float* Ap = A + (size_t)(m0 + lr) * K + lk;
    const float* Wp = W + (size_t)(n0 + lr) * K + lk;
    float4 pa = *reinterpret_cast<const float4*>(Ap);
    float4 pb = *reinterpret_cast<const float4*>(Wp);

    for (int k0 = 0; k0 < K; k0 += 8) {
        As[lk + 0][lr] = pa.x; As[lk + 1][lr] = pa.y;
        As[lk + 2][lr] = pa.z; As[lk + 3][lr] = pa.w;
        Bs[lk + 0][lr] = pb.x; Bs[lk + 1][lr] = pb.y;
        Bs[lk + 2][lr] = pb.z; Bs[lk + 3][lr] = pb.w;
        __syncthreads();
        if (k0 + 8 < K) {
            pa = *reinterpret_cast<const float4*>(Ap + k0 + 8);
            pb = *reinterpret_cast<const float4*>(Wp + k0 + 8);
        }
#pragma unroll
        for (int kk = 0; kk < 8; ++kk) {
            float4 a0 = *reinterpret_cast<const float4*>(&As[kk][ty * 4]);
            float4 a1 = *reinterpret_cast<const float4*>(&As[kk][64 + ty * 4]);
            float4 b0 = *reinterpret_cast<const float4*>(&Bs[kk][tx * 4]);
            float4 b1 = *reinterpret_cast<const float4*>(&Bs[kk][64 + tx * 4]);
            float am[8] = {a0.x, a0.y, a0.z, a0.w, a1.x, a1.y, a1.z, a1.w};
            float bn[8] = {b0.x, b0.y, b0.z, b0.w, b1.x, b1.y, b1.z, b1.w};
#pragma unroll
            for (int i = 0; i < 8; ++i)
#pragma unroll
                for (int j = 0; j < 8; ++j)
                    acc[i][j] += am[i] * bn[j];
        }
        __syncthreads();
    }

    const int nc0 = n0 + tx * 4;
    const int nc1 = n0 + 64 + tx * 4;
    float bs0[4], bs1[4];
#pragma unroll
    for (int j = 0; j < 4; ++j) {
        bs0[j] = bih[nc0 + j] + bhh[nc0 + j];
        bs1[j] = bih[nc1 + j] + bhh[nc1 + j];
    }
#pragma unroll
    for (int i = 0; i < 8; ++i) {
        int m = m0 + ((i < 4) ? (ty * 4 + i) : (64 + ty * 4 + i - 4));
        float4 v0, v1;
        v0.x = acc[i][0] + bs0[0]; v0.y = acc[i][1] + bs0[1];
        v0.z = acc[i][2] + bs0[2]; v0.w = acc[i][3] + bs0[3];
        v1.x = acc[i][4] + bs1[0]; v1.y = acc[i][5] + bs1[1];
        v1.z = acc[i][6] + bs1[2]; v1.w = acc[i][7] + bs1[3];
        *reinterpret_cast<float4*>(C + (size_t)m * Gq + nc0) = v0;
        *reinterpret_cast<float4*>(C + (size_t)m * Gq + nc1) = v1;
    }
}

// ---------------- persistent recurrent scan (one launch per layer) ------
// Grid = 128 CTAs; CTA owns 4 h-columns j0..j0+3 => 16 gate rows.
// Whh rows live in SMEM for the whole layer. h double-buffered in global.
__global__ void __launch_bounds__(SCAN_TPB) lstm_scan_kernel(
    const float* __restrict__ gx,   // [b][s][2048]
    const float* __restrict__ Whh,  // [2048][512] this layer
    float* __restrict__ out)        // [b][s][512]
{
    extern __shared__ float sm[];
    float* Wsh = sm;                   // 16 * 512
    float* hsh = Wsh + 16 * Hq;        // 32 * HPAD
    float* gsh = hsh + Bq * HPAD;      // 16 * 33
    float* csh = gsh + 16 * 33;        // 128

    const int tid = threadIdx.x;
    const int j0 = blockIdx.x * 4;

    // load this CTA's 16 Whh rows: local row r -> global row (r>>2)*512 + j0 + (r&3)
    for (int i = tid; i < 16 * (Hq / 4); i += SCAN_TPB) {
        int r = i / (Hq / 4);
        int k4 = i % (Hq / 4);
        int grow = (r >> 2) * Hq + j0 + (r & 3);
        reinterpret_cast<float4*>(Wsh + r * Hq)[k4] =
            reinterpret_cast<const float4*>(Whh + (size_t)grow * Hq)[k4];
    }
    if (tid < 128) csh[tid] = 0.f;
    __syncthreads();

    const int b  = tid & 31;   // dot-thread batch
    const int rp = tid >> 5;   // dot-thread row-pair base (0..7)

    for (int t = 0; t < Sq; ++t) {
        const int cur = t & 1, nxt = cur ^ 1;

        // prefetch gx for the gate stage (latency hidden behind staging+dots)
        float gxv0 = 0.f, gxv1 = 0.f, gxv2 = 0.f, gxv3 = 0.f;
        if (tid < 128) {
            const int gb = tid & 31, gjj = tid >> 5;
            const float* gp = gx + ((size_t)gb * Sq + t) * Gq + j0 + gjj;
            gxv0 = gp[0]; gxv1 = gp[Hq]; gxv2 = gp[2 * Hq]; gxv3 = gp[3 * Hq];
        }

        float acc0 = 0.f, acc1 = 0.f;
        if (t > 0) {
            // stage h[cur] ([k][b] in gmem) into hsh[b][k] (padded)
            const float* hsrc = g_hbuf[cur];
            for (int i = tid; i < Hq * Bq; i += SCAN_TPB) {
                hsh[(i & 31) * HPAD + (i >> 5)] = hsrc[i];
            }
            __syncthreads();
            const float* hp = hsh + b * HPAD;
            const float* w0 = Wsh + rp * Hq;
            const float* w1 = Wsh + (rp + 8) * Hq;
#pragma unroll 4
            for (int k = 0; k < Hq; k += 4) {
                float4 hv = *reinterpret_cast<const float4*>(hp + k);
                float4 wa = *reinterpret_cast<const float4*>(w0 + k);
                float4 wb = *reinterpret_cast<const float4*>(w1 + k);
                acc0 += hv.x * wa.x; acc1 += hv.x * wb.x;
                acc0 += hv.y * wa.y; acc1 += hv.y * wb.y;
                acc0 += hv.z * wa.z; acc1 += hv.z * wb.z;
                acc0 += hv.w * wa.w; acc1 += hv.w * wb.w;
            }
        }
        gsh[rp * 33 + b] = acc0;
        gsh[(rp + 8) * 33 + b] = acc1;
        __syncthreads();

        if (tid < 128) {
            const int gb = tid & 31, gjj = tid >> 5;
            float iv = gsh[gjj * 33 + gb]        + gxv0;
            float fv = gsh[(4 + gjj) * 33 + gb]  + gxv1;
            float gv = gsh[(8 + gjj) * 33 + gb]  + gxv2;
            float ov = gsh[(12 + gjj) * 33 + gb] + gxv3;
            float si = 1.f / (1.f + __expf(-iv));
            float sf = 1.f / (1.f + __expf(-fv));
            float so = 1.f / (1.f + __expf(-ov));
            float tg = tanhf(gv);
            float c  = sf * csh[tid] + si * tg;
            csh[tid] = c;
            float hn = so * tanhf(c);
            g_hbuf[nxt][(j0 + gjj) * Bq + gb] = hn;
            out[((size_t)gb * Sq + t) * Hq + j0 + gjj] = hn;
        }
        grid_barrier();  // h[nxt] visible to all CTAs before next step
    }
}

// ---------------- softmax over sequence axis (per (b,h) column) ---------
__global__ void __launch_bounds__(256) softmax_kernel(
    const float* __restrict__ in, float* __restrict__ probs)
{
    int gw = (blockIdx.x * 256 + threadIdx.x) >> 5;  // 0..16383
    int lane = threadIdx.x & 31;
    int bb = gw >> 9;       // /512
    int hh = gw & 511;
    const float* p = in + (size_t)bb * Sq * Hq + hh;
    float v[8];
    float mx = -3.4e38f;
#pragma unroll
    for (int i = 0; i < 8; ++i) {
        v[i] = p[(size_t)(lane + 32 * i) * Hq];
        mx = fmaxf(mx, v[i]);
    }
#pragma unroll
    for (int o = 16; o; o >>= 1) mx = fmaxf(mx, __shfl_xor_sync(0xffffffffu, mx, o));
    float sum = 0.f;
#pragma unroll
    for (int i = 0; i < 8; ++i) { v[i] = __expf(v[i] - mx); sum += v[i]; }
#pragma unroll
    for (int o = 16; o; o >>= 1) sum += __shfl_xor_sync(0xffffffffu, sum, o);
    float inv = 1.f / sum;
    float* q = probs + (size_t)bb * Sq * Hq + hh;
#pragma unroll
    for (int i = 0; i < 8; ++i) q[(size_t)(lane + 32 * i) * Hq] = v[i] * inv;
}

// ---------------- final FC: out[b][s][c] = probs[b][s][:]·Wfc[c][:]+bfc --
__global__ void __launch_bounds__(256) fc_kernel(
    const float* __restrict__ probs, const float* __restrict__ Wfc,
    const float* __restrict__ bfc, float* __restrict__ out)
{
    int gw = (blockIdx.x * 256 + threadIdx.x) >> 5;  // 0..8191 = (b,s)
    int lane = threadIdx.x & 31;
    const float* p = probs + (size_t)gw * Hq;
    float a0 = 0.f, a1 = 0.f, a2 = 0.f, a3 = 0.f;
    for (int k = lane; k < Hq; k += 32) {
        float pv = p[k];
        a0 += pv * Wfc[k];
        a1 += pv * Wfc[Hq + k];
        a2 += pv * Wfc[2 * Hq + k];
        a3 += pv * Wfc[3 * Hq + k];
    }
#pragma unroll
    for (int o = 16; o; o >>= 1) {
        a0 += __shfl_xor_sync(0xffffffffu, a0, o);
        a1 += __shfl_xor_sync(0xffffffffu, a1, o);
        a2 += __shfl_xor_sync(0xffffffffu, a2, o);
        a3 += __shfl_xor_sync(0xffffffffu, a3, o);
    }
    if (lane == 0) {
        float4 r;
        r.x = a0 + bfc[0]; r.y = a1 + bfc[1];
        r.z = a2 + bfc[2]; r.w = a3 + bfc[3];
        *reinterpret_cast<float4*>(out + (size_t)gw * 4) = r;
    }
}

// ---------------- launcher -----------------------------------------------
extern "C" void kernel_launch(void* const* d_in, const int* in_sizes, int n_in,
                              void* d_out, int out_size)
{
    const float* x    = (const float*)d_in[0];  // [32,256,256]
    const float* Wih0 = (const float*)d_in[1];  // [2048,256]
    const float* WihR = (const float*)d_in[2];  // [3,2048,512]
    const float* Whh  = (const float*)d_in[3];  // [4,2048,512]
    const float* bih  = (const float*)d_in[4];  // [4,2048]
    const float* bhh  = (const float*)d_in[5];  // [4,2048]
    const float* Wfc  = (const float*)d_in[6];  // [4,512]
    const float* bfc  = (const float*)d_in[7];  // [4]
    float* out = (float*)d_out;                 // [32,256,4] f32

    float *gx, *io0, *io1;
    cudaGetSymbolAddress((void**)&gx,  g_gx);
    cudaGetSymbolAddress((void**)&io0, g_io0);
    cudaGetSymbolAddress((void**)&io1, g_io1);

    cudaFuncSetAttribute(lstm_scan_kernel,
                         cudaFuncAttributeMaxDynamicSharedMemorySize,
                         SCAN_SMEM_BYTES);

    const float* lin[4]  = {x, io0, io1, io0};
    float*       lout[4] = {io0, io1, io0, io1};

    for (int l = 0; l < 4; ++l) {
        int K = (l == 0) ? Eq : Hq;
        const float* Wih = (l == 0) ? Wih0 : (WihR + (size_t)(l - 1) * Gq * Hq);
        gemm_kernel<<<dim3(Gq / 128, M_TOT / 128), 256>>>(
            lin[l], Wih, bih + (size_t)l * Gq, bhh + (size_t)l * Gq, gx, K);
        lstm_scan_kernel<<<SCAN_NCTA, SCAN_TPB, SCAN_SMEM_BYTES>>>(
            gx, Whh + (size_t)l * Gq * Hq, lout[l]);
    }

    // softmax over S into g_gx (reused as probs), then FC
    softmax_kernel<<<2048, 256>>>(io1, gx);
    fc_kernel<<<1024, 256>>>(gx, Wfc, bfc, out);
}

// round 3
// speedup vs baseline: 1.0280x; 1.0280x over previous
#include <cuda_runtime.h>
#include <cstdint>

#define Bq 32
#define Sq 256
#define Eq 256
#define Hq 512
#define Gq 2048          // 4*H
#define M_TOT (Bq * Sq)  // 8192

#define SCAN_NCTA 128
#define SCAN_TPB  256
#define HPAD      516    // 516%8(16B-chunks)=... (b*129+kq)%8 distinct -> conflict-free
#define SCAN_SMEM_FLOATS (16 * Hq + Bq * HPAD + 16 * 33 + 128)
#define SCAN_SMEM_BYTES  (SCAN_SMEM_FLOATS * 4)

typedef unsigned long long ull;

// packed f32x2 helpers (sm_103a FFMA2 path)
#define FMA2(acc, a, b) \
    asm("fma.rn.f32x2 %0, %1, %2, %0;" : "+l"(acc) : "l"(a), "l"(b))
#define DUP2(d, s) \
    asm("mov.b64 %0, {%1, %1};" : "=l"(d) : "f"(s))
#define UNPK2(lo, hi, v) \
    asm("mov.b64 {%0, %1}, %2;" : "=f"(lo), "=f"(hi) : "l"(v))

// ---------------- device scratch (static, no allocation) ----------------
__device__ float g_gx[M_TOT * Gq];     // 64MB gate pre-activations; reused as probs
__device__ float g_io0[M_TOT * Hq];    // 16MB layer ping
__device__ float g_io1[M_TOT * Hq];    // 16MB layer pong
__device__ float g_hbuf[2][Bq * Hq];   // recurrent h double buffer, layout [b][k]
__device__ unsigned g_bar_count = 0;
__device__ volatile unsigned g_bar_gen = 0;

// ---------------- software grid barrier (all CTAs co-resident) ----------
__device__ __forceinline__ void grid_barrier() {
    __syncthreads();
    if (threadIdx.x == 0) {
        __threadfence();
        unsigned old = g_bar_gen;          // read BEFORE arriving
        unsigned prev = atomicAdd(&g_bar_count, 1u);
        if (prev == gridDim.x - 1) {
            atomicExch(&g_bar_count, 0u);
            __threadfence();
            g_bar_gen = old + 1;
        } else {
            while (g_bar_gen == old) { }   // volatile poll, no atomic RT
        }
        __threadfence();
    }
    __syncthreads();
}

// ---------------- input GEMM: C[m][g] = A[m][:]·W[g][:] + bih[g]+bhh[g] --
// A: [8192][K] row-major, W: [2048][K] row-major, C: [8192][2048]
__global__ void __launch_bounds__(256) gemm_kernel(
    const float* __restrict__ A, const float* __restrict__ W,
    const float* __restrict__ bih, const float* __restrict__ bhh,
    float* __restrict__ C, int K)
{
    __shared__ float As[8][128];
    __shared__ float Bs[8][128];
    const int tid = threadIdx.x;
    const int m0 = blockIdx.y * 128;
    const int n0 = blockIdx.x * 128;
    const int lr = tid >> 1;
    const int lk = (tid & 1) * 4;
    const int tx = tid & 15;
    const int ty = tid >> 4;

    ull acc2[8][4];
#pragma unroll
    for (int i = 0; i < 8; ++i)
#pragma unroll
        for (int j = 0; j < 4; ++j) acc2[i][j] = 0ull;

    const float* Ap = A + (size_t)(m0 + lr) * K + lk;
    const float* Wp = W + (size_t)(n0 + lr) * K + lk;
    float4 pa = *reinterpret_cast<const float4*>(Ap);
    float4 pb = *reinterpret_cast<const float4*>(Wp);

    for (int k0 = 0; k0 < K; k0 += 8) {
        As[lk + 0][lr] = pa.x; As[lk + 1][lr] = pa.y;
        As[lk + 2][lr] = pa.z; As[lk + 3][lr] = pa.w;
        Bs[lk + 0][lr] = pb.x; Bs[lk + 1][lr] = pb.y;
        Bs[lk + 2][lr] = pb.z; Bs[lk + 3][lr] = pb.w;
        __syncthreads();
        if (k0 + 8 < K) {
            pa = *reinterpret_cast<const float4*>(Ap + k0 + 8);
            pb = *reinterpret_cast<const float4*>(Wp + k0 + 8);
        }
#pragma unroll
        for (int kk = 0; kk < 8; ++kk) {
            float4 a0 = *reinterpret_cast<const float4*>(&As[kk][ty * 4]);
            float4 a1 = *reinterpret_cast<const float4*>(&As[kk][64 + ty * 4]);
            ulonglong2 bb0 = *reinterpret_cast<const ulonglong2*>(&Bs[kk][tx * 4]);
            ulonglong2 bb1 = *reinterpret_cast<const ulonglong2*>(&Bs[kk][64 + tx * 4]);
            float am[8] = {a0.x, a0.y, a0.z, a0.w, a1.x, a1.y, a1.z, a1.w};
            ull bp0 = bb0.x, bp1 = bb0.y, bp2 = bb1.x, bp3 = bb1.y;
#pragma unroll
            for (int i = 0; i < 8; ++i) {
                ull a2; DUP2(a2, am[i]);
                FMA2(acc2[i][0], a2, bp0);
                FMA2(acc2[i][1], a2, bp1);
                FMA2(acc2[i][2], a2, bp2);
                FMA2(acc2[i][3], a2, bp3);
            }
        }
        __syncthreads();
    }

    float acc[8][8];
#pragma unroll
    for (int i = 0; i < 8; ++i)
#pragma unroll
        for (int j = 0; j < 4; ++j)
            UNPK2(acc[i][2 * j], acc[i][2 * j + 1], acc2[i][j]);

    const int nc0 = n0 + tx * 4;
    const int nc1 = n0 + 64 + tx * 4;
    float bs0[4], bs1[4];
#pragma unroll
    for (int j = 0; j < 4; ++j) {
        bs0[j] = bih[nc0 + j] + bhh[nc0 + j];
        bs1[j] = bih[nc1 + j] + bhh[nc1 + j];
    }
#pragma unroll
    for (int i = 0; i < 8; ++i) {
        int m = m0 + ((i < 4) ? (ty * 4 + i) : (64 + ty * 4 + i - 4));
        float4 v0, v1;
        v0.x = acc[i][0] + bs0[0]; v0.y = acc[i][1] + bs0[1];
        v0.z = acc[i][2] + bs0[2]; v0.w = acc[i][3] + bs0[3];
        v1.x = acc[i][4] + bs1[0]; v1.y = acc[i][5] + bs1[1];
        v1.z = acc[i][6] + bs1[2]; v1.w = acc[i][7] + bs1[3];
        *reinterpret_cast<float4*>(C + (size_t)m * Gq + nc0) = v0;
        *reinterpret_cast<float4*>(C + (size_t)m * Gq + nc1) = v1;
    }
}

// ---------------- persistent recurrent scan (one launch per layer) ------
// Grid = 128 CTAs; CTA owns 4 h-columns j0..j0+3 => 16 gate rows.
// Whh rows live in SMEM for the whole layer. h double-buffered in global [b][k].
__global__ void __launch_bounds__(SCAN_TPB) lstm_scan_kernel(
    const float* __restrict__ gx,   // [b][s][2048]
    const float* __restrict__ Whh,  // [2048][512] this layer
    float* __restrict__ out)        // [b][s][512]
{
    extern __shared__ float sm[];
    float* Wsh = sm;                   // 16 * 512
    float* hsh = Wsh + 16 * Hq;        // 32 * HPAD
    float* gsh = hsh + Bq * HPAD;      // 16 * 33
    float* csh = gsh + 16 * 33;        // 128

    const int tid = threadIdx.x;
    const int j0 = blockIdx.x * 4;

    // load this CTA's 16 Whh rows: local row r -> global row (r>>2)*512 + j0 + (r&3)
    for (int i = tid; i < 16 * (Hq / 4); i += SCAN_TPB) {
        int r = i / (Hq / 4);
        int k4 = i % (Hq / 4);
        int grow = (r >> 2) * Hq + j0 + (r & 3);
        reinterpret_cast<float4*>(Wsh + r * Hq)[k4] =
            reinterpret_cast<const float4*>(Whh + (size_t)grow * Hq)[k4];
    }
    if (tid < 128) csh[tid] = 0.f;
    __syncthreads();

    const int b  = tid & 31;   // dot-thread batch
    const int rp = tid >> 5;   // dot-thread row-pair base (0..7)
    const int gb = tid & 31;   // gate-thread batch
    const int gjj = (tid >> 5) & 3;

    // prefetch gx for t=0
    float gxv0 = 0.f, gxv1 = 0.f, gxv2 = 0.f, gxv3 = 0.f;
    if (tid < 128) {
        const float* gp = gx + ((size_t)gb * Sq + 0) * Gq + j0 + gjj;
        gxv0 = gp[0]; gxv1 = gp[Hq]; gxv2 = gp[2 * Hq]; gxv3 = gp[3 * Hq];
    }

    for (int t = 0; t < Sq; ++t) {
        const int cur = t & 1, nxt = cur ^ 1;

        float acc0 = 0.f, acc1 = 0.f;
        if (t > 0) {
            // stage h[cur] ([b][k] gmem) -> hsh[b][k] (padded). Coalesced LDG,
            // conflict-free STS (consecutive lanes -> consecutive k).
            const float4* hsrc = reinterpret_cast<const float4*>(g_hbuf[cur]);
            for (int q = tid; q < (Hq * Bq) / 4; q += SCAN_TPB) {
                int bb2 = q >> 7;     // /128 float4s per b-row
                int kq  = q & 127;
                *reinterpret_cast<float4*>(hsh + bb2 * HPAD + kq * 4) = hsrc[q];
            }
            __syncthreads();

            const ulonglong2* hp2 = reinterpret_cast<const ulonglong2*>(hsh + b * HPAD);
            const ulonglong2* w0  = reinterpret_cast<const ulonglong2*>(Wsh + rp * Hq);
            const ulonglong2* w1  = reinterpret_cast<const ulonglong2*>(Wsh + (rp + 8) * Hq);
            ull acc2a = 0ull, acc2b = 0ull;
#pragma unroll 4
            for (int k4 = 0; k4 < Hq / 4; ++k4) {
                ulonglong2 hv = hp2[k4];
                ulonglong2 wa = w0[k4];
                ulonglong2 wb = w1[k4];
                FMA2(acc2a, hv.x, wa.x);
                FMA2(acc2b, hv.x, wb.x);
                FMA2(acc2a, hv.y, wa.y);
                FMA2(acc2b, hv.y, wb.y);
            }
            float lo, hi;
            UNPK2(lo, hi, acc2a); acc0 = lo + hi;
            UNPK2(lo, hi, acc2b); acc1 = lo + hi;
        }
        gsh[rp * 33 + b] = acc0;
        gsh[(rp + 8) * 33 + b] = acc1;
        __syncthreads();

        if (tid < 128) {
            float iv = gsh[gjj * 33 + gb]        + gxv0;
            float fv = gsh[(4 + gjj) * 33 + gb]  + gxv1;
            float gv = gsh[(8 + gjj) * 33 + gb]  + gxv2;
            float ov = gsh[(12 + gjj) * 33 + gb] + gxv3;
            float si = 1.f / (1.f + __expf(-iv));
            float sf = 1.f / (1.f + __expf(-fv));
            float so = 1.f / (1.f + __expf(-ov));
            float tg = tanhf(gv);
            float c  = sf * csh[tid] + si * tg;
            csh[tid] = c;
            float hn = so * tanhf(c);
            g_hbuf[nxt][gb * Hq + j0 + gjj] = hn;                      // [b][k]
            out[((size_t)gb * Sq + t) * Hq + j0 + gjj] = hn;

            // prefetch gx for t+1 BEFORE the barrier (hide DRAM latency)
            int tn = (t + 1 < Sq) ? t + 1 : t;
            const float* gp = gx + ((size_t)gb * Sq + tn) * Gq + j0 + gjj;
            gxv0 = gp[0]; gxv1 = gp[Hq]; gxv2 = gp[2 * Hq]; gxv3 = gp[3 * Hq];
        }
        grid_barrier();  // h[nxt] visible to all CTAs before next step
    }
}

// ---------------- softmax over sequence axis (per (b,h) column) ---------
__global__ void __launch_bounds__(256) softmax_kernel(
    const float* __restrict__ in, float* __restrict__ probs)
{
    int gw = (blockIdx.x * 256 + threadIdx.x) >> 5;  // 0..16383
    int lane = threadIdx.x & 31;
    int bb = gw >> 9;       // /512
    int hh = gw & 511;
    const float* p = in + (size_t)bb * Sq * Hq + hh;
    float v[8];
    float mx = -3.4e38f;
#pragma unroll
    for (int i = 0; i < 8; ++i) {
        v[i] = p[(size_t)(lane + 32 * i) * Hq];
        mx = fmaxf(mx, v[i]);
    }
#pragma unroll
    for (int o = 16; o; o >>= 1) mx = fmaxf(mx, __shfl_xor_sync(0xffffffffu, mx, o));
    float sum = 0.f;
#pragma unroll
    for (int i = 0; i < 8; ++i) { v[i] = __expf(v[i] - mx); sum += v[i]; }
#pragma unroll
    for (int o = 16; o; o >>= 1) sum += __shfl_xor_sync(0xffffffffu, sum, o);
    float inv = 1.f / sum;
    float* q = probs + (size_t)bb * Sq * Hq + hh;
#pragma unroll
    for (int i = 0; i < 8; ++i) q[(size_t)(lane + 32 * i) * Hq] = v[i] * inv;
}

// ---------------- final FC: out[b][s][c] = probs[b][s][:]·Wfc[c][:]+bfc --
__global__ void __launch_bounds__(256) fc_kernel(
    const float* __restrict__ probs, const float* __restrict__ Wfc,
    const float* __restrict__ bfc, float* __restrict__ out)
{
    int gw = (blockIdx.x * 256 + threadIdx.x) >> 5;  // 0..8191 = (b,s)
    int lane = threadIdx.x & 31;
    const float* p = probs + (size_t)gw * Hq;
    float a0 = 0.f, a1 = 0.f, a2 = 0.f, a3 = 0.f;
    for (int k = lane; k < Hq; k += 32) {
        float pv = p[k];
        a0 += pv * Wfc[k];
        a1 += pv * Wfc[Hq + k];
        a2 += pv * Wfc[2 * Hq + k];
        a3 += pv * Wfc[3 * Hq + k];
    }
#pragma unroll
    for (int o = 16; o; o >>= 1) {
        a0 += __shfl_xor_sync(0xffffffffu, a0, o);
        a1 += __shfl_xor_sync(0xffffffffu, a1, o);
        a2 += __shfl_xor_sync(0xffffffffu, a2, o);
        a3 += __shfl_xor_sync(0xffffffffu, a3, o);
    }
    if (lane == 0) {
        float4 r;
        r.x = a0 + bfc[0]; r.y = a1 + bfc[1];
        r.z = a2 + bfc[2]; r.w = a3 + bfc[3];
        *reinterpret_cast<float4*>(out + (size_t)gw * 4) = r;
    }
}

// ---------------- launcher -----------------------------------------------
extern "C" void kernel_launch(void* const* d_in, const int* in_sizes, int n_in,
                              void* d_out, int out_size)
{
    const float* x    = (const float*)d_in[0];  // [32,256,256]
    const float* Wih0 = (const float*)d_in[1];  // [2048,256]
    const float* WihR = (const float*)d_in[2];  // [3,2048,512]
    const float* Whh  = (const float*)d_in[3];  // [4,2048,512]
    const float* bih  = (const float*)d_in[4];  // [4,2048]
    const float* bhh  = (const float*)d_in[5];  // [4,2048]
    const float* Wfc  = (const float*)d_in[6];  // [4,512]
    const float* bfc  = (const float*)d_in[7];  // [4]
    float* out = (float*)d_out;                 // [32,256,4] f32

    float *gx, *io0, *io1;
    cudaGetSymbolAddress((void**)&gx,  g_gx);
    cudaGetSymbolAddress((void**)&io0, g_io0);
    cudaGetSymbolAddress((void**)&io1, g_io1);

    cudaFuncSetAttribute(lstm_scan_kernel,
                         cudaFuncAttributeMaxDynamicSharedMemorySize,
                         SCAN_SMEM_BYTES);

    const float* lin[4]  = {x, io0, io1, io0};
    float*       lout[4] = {io0, io1, io0, io1};

    for (int l = 0; l < 4; ++l) {
        int K = (l == 0) ? Eq : Hq;
        const float* Wih = (l == 0) ? Wih0 : (WihR + (size_t)(l - 1) * Gq * Hq);
        gemm_kernel<<<dim3(Gq / 128, M_TOT / 128), 256>>>(
            lin[l], Wih, bih + (size_t)l * Gq, bhh + (size_t)l * Gq, gx, K);
        lstm_scan_kernel<<<SCAN_NCTA, SCAN_TPB, SCAN_SMEM_BYTES>>>(
            gx, Whh + (size_t)l * Gq * Hq, lout[l]);
    }

    // softmax over S into g_gx (reused as probs), then FC
    softmax_kernel<<<2048, 256>>>(io1, gx);
    fc_kernel<<<1024, 256>>>(gx, Wfc, bfc, out);
}

// round 4
// speedup vs baseline: 1.6873x; 1.6414x over previous
#include <cuda_runtime.h>
#include <cstdint>

#define Bq 32
#define Sq 256
#define Eq 256
#define Hq 512
#define Gq 2048          // 4*H
#define M_TOT (Bq * Sq)  // 8192

#define SCAN_NCTA 128
#define SCAN_TPB  256
#define HP 132           // hsh row pad (floats): conflict-free LDS.128 per-b rows

// SMEM: Wsh 16*512 | hsh 32*132 | part 8*16*33 | csh 128
#define SCAN_SMEM_FLOATS (16 * Hq + Bq * HP + 8 * 16 * 33 + 128)
#define SCAN_SMEM_BYTES  (SCAN_SMEM_FLOATS * 4)

typedef unsigned long long ull;

// packed f32x2 helpers (sm_103a FFMA2 path)
#define FMA2(acc, a, b) \
    asm("fma.rn.f32x2 %0, %1, %2, %0;" : "+l"(acc) : "l"(a), "l"(b))
#define DUP2(d, s) \
    asm("mov.b64 %0, {%1, %1};" : "=l"(d) : "f"(s))
#define UNPK2(lo, hi, v) \
    asm("mov.b64 {%0, %1}, %2;" : "=f"(lo), "=f"(hi) : "l"(v))

// ---------------- device scratch (static, no allocation) ----------------
__device__ float g_gx[M_TOT * Gq];       // 64MB gate pre-activations; reused as probs
__device__ float g_io0[M_TOT * Hq];      // 16MB layer ping
__device__ float g_io1[M_TOT * Hq];      // 16MB layer pong
__device__ float g_h[2][Bq * Hq];        // recurrent h double buffer, [b][k]
__device__ volatile unsigned g_flags[2][SCAN_NCTA * 32];  // per-CTA padded flags

// ---------------- input GEMM: C[m][g] = A[m][:]·W[g][:] + bih[g]+bhh[g] --
__global__ void __launch_bounds__(256) gemm_kernel(
    const float* __restrict__ A, const float* __restrict__ W,
    const float* __restrict__ bih, const float* __restrict__ bhh,
    float* __restrict__ C, int K)
{
    __shared__ float As[8][128];
    __shared__ float Bs[8][128];
    const int tid = threadIdx.x;
    const int m0 = blockIdx.y * 128;
    const int n0 = blockIdx.x * 128;
    const int lr = tid >> 1;
    const int lk = (tid & 1) * 4;
    const int tx = tid & 15;
    const int ty = tid >> 4;

    ull acc2[8][4];
#pragma unroll
    for (int i = 0; i < 8; ++i)
#pragma unroll
        for (int j = 0; j < 4; ++j) acc2[i][j] = 0ull;

    const float* Ap = A + (size_t)(m0 + lr) * K + lk;
    const float* Wp = W + (size_t)(n0 + lr) * K + lk;
    float4 pa = *reinterpret_cast<const float4*>(Ap);
    float4 pb = *reinterpret_cast<const float4*>(Wp);

    for (int k0 = 0; k0 < K; k0 += 8) {
        As[lk + 0][lr] = pa.x; As[lk + 1][lr] = pa.y;
        As[lk + 2][lr] = pa.z; As[lk + 3][lr] = pa.w;
        Bs[lk + 0][lr] = pb.x; Bs[lk + 1][lr] = pb.y;
        Bs[lk + 2][lr] = pb.z; Bs[lk + 3][lr] = pb.w;
        __syncthreads();
        if (k0 + 8 < K) {
            pa = *reinterpret_cast<const float4*>(Ap + k0 + 8);
            pb = *reinterpret_cast<const float4*>(Wp + k0 + 8);
        }
#pragma unroll
        for (int kk = 0; kk < 8; ++kk) {
            float4 a0 = *reinterpret_cast<const float4*>(&As[kk][ty * 4]);
            float4 a1 = *reinterpret_cast<const float4*>(&As[kk][64 + ty * 4]);
            ulonglong2 bb0 = *reinterpret_cast<const ulonglong2*>(&Bs[kk][tx * 4]);
            ulonglong2 bb1 = *reinterpret_cast<const ulonglong2*>(&Bs[kk][64 + tx * 4]);
            float am[8] = {a0.x, a0.y, a0.z, a0.w, a1.x, a1.y, a1.z, a1.w};
            ull bp0 = bb0.x, bp1 = bb0.y, bp2 = bb1.x, bp3 = bb1.y;
#pragma unroll
            for (int i = 0; i < 8; ++i) {
                ull a2; DUP2(a2, am[i]);
                FMA2(acc2[i][0], a2, bp0);
                FMA2(acc2[i][1], a2, bp1);
                FMA2(acc2[i][2], a2, bp2);
                FMA2(acc2[i][3], a2, bp3);
            }
        }
        __syncthreads();
    }

    float acc[8][8];
#pragma unroll
    for (int i = 0; i < 8; ++i)
#pragma unroll
        for (int j = 0; j < 4; ++j)
            UNPK2(acc[i][2 * j], acc[i][2 * j + 1], acc2[i][j]);

    const int nc0 = n0 + tx * 4;
    const int nc1 = n0 + 64 + tx * 4;
    float bs0[4], bs1[4];
#pragma unroll
    for (int j = 0; j < 4; ++j) {
        bs0[j] = bih[nc0 + j] + bhh[nc0 + j];
        bs1[j] = bih[nc1 + j] + bhh[nc1 + j];
    }
#pragma unroll
    for (int i = 0; i < 8; ++i) {
        int m = m0 + ((i < 4) ? (ty * 4 + i) : (64 + ty * 4 + i - 4));
        float4 v0, v1;
        v0.x = acc[i][0] + bs0[0]; v0.y = acc[i][1] + bs0[1];
        v0.z = acc[i][2] + bs0[2]; v0.w = acc[i][3] + bs0[3];
        v1.x = acc[i][4] + bs1[0]; v1.y = acc[i][5] + bs1[1];
        v1.z = acc[i][6] + bs1[2]; v1.w = acc[i][7] + bs1[3];
        *reinterpret_cast<float4*>(C + (size_t)m * Gq + nc0) = v0;
        *reinterpret_cast<float4*>(C + (size_t)m * Gq + nc1) = v1;
    }
}

// ---------------- persistent recurrent scan (one launch per layer) ------
// 128 CTAs co-resident (<=148 SMs). CTA owns 4 h-cols (16 gate rows).
// Sync via per-CTA padded flags (no atomics, no shared-counter contention).
__global__ void __launch_bounds__(SCAN_TPB) lstm_scan_kernel(
    const float* __restrict__ gx,   // [b][s][2048]
    const float* __restrict__ Whh,  // [2048][512] this layer
    float* __restrict__ out,        // [b][s][512]
    unsigned ebase)                 // layer * Sq (epoch base)
{
    extern __shared__ float sm[];
    float* Wsh  = sm;                      // 16 * 512
    float* hsh  = Wsh + 16 * Hq;           // 32 * HP
    float* part = hsh + Bq * HP;           // 8 * 16 * 33
    float* csh  = part + 8 * 16 * 33;      // 128

    const int tid  = threadIdx.x;
    const int cta  = blockIdx.x;
    const int j0   = cta * 4;
    const int wid  = tid >> 5;
    const int lane = tid & 31;

    // load this CTA's 16 Whh rows: local r -> global row (r>>2)*512 + j0 + (r&3)
    for (int i = tid; i < 16 * (Hq / 4); i += SCAN_TPB) {
        int r  = i / (Hq / 4);
        int k4 = i % (Hq / 4);
        int grow = (r >> 2) * Hq + j0 + (r & 3);
        reinterpret_cast<float4*>(Wsh + r * Hq)[k4] =
            reinterpret_cast<const float4*>(Whh + (size_t)grow * Hq)[k4];
    }
    if (tid < 128) csh[tid] = 0.f;
    __syncthreads();

    const int gb  = tid & 31;          // gate-thread batch
    const int gjj = (tid >> 5) & 3;    // gate-thread column (tid<128)

    // prefetch gx for t=0
    float gxv0 = 0.f, gxv1 = 0.f, gxv2 = 0.f, gxv3 = 0.f;
    if (tid < 128) {
        const float* gp = gx + (size_t)gb * Sq * Gq + j0 + gjj;
        gxv0 = gp[0]; gxv1 = gp[Hq]; gxv2 = gp[2 * Hq]; gxv3 = gp[3 * Hq];
    }

    for (int t = 0; t < Sq; ++t) {
        const int cur = t & 1, nxt = cur ^ 1;

        if (t > 0) {
            // ---- wait: all CTAs published h_t (flags[cur][*] == ebase+t) ----
            if (wid == 7) {
                unsigned target = ebase + (unsigned)t;
                volatile unsigned* f = &g_flags[cur][0];
                bool done = false;
                do {
                    bool ok = true;
#pragma unroll
                    for (int i = 0; i < 4; ++i)
                        ok &= (f[(lane * 4 + i) * 32] == target);
                    done = __all_sync(0xffffffffu, ok);
                } while (!done);
                __threadfence();
            }
            __syncthreads();

            // ---- stage h_t: g_h[cur] ([b][k]) -> hsh[b][k] (pad HP) ----
            const float4* hsrc = reinterpret_cast<const float4*>(g_h[cur]);
#pragma unroll
            for (int i = 0; i < (Bq * Hq / 4) / SCAN_TPB; ++i) {
                int q  = i * SCAN_TPB + tid;
                int bb = q >> 7;       // /128 float4 per b-row
                int kq = q & 127;
                *reinterpret_cast<float4*>(hsh + bb * HP + kq * 4) = hsrc[q];
            }
            __syncthreads();

            // ---- dot: warp wid -> k chunk [wid*64, wid*64+64), all 16 rows ----
            {
                const int kbase = wid * 64;
                const int b = lane;
                ull acc2[16];
#pragma unroll
                for (int r = 0; r < 16; ++r) acc2[r] = 0ull;
#pragma unroll 4
                for (int k4 = 0; k4 < 16; ++k4) {
                    int k = kbase + k4 * 4;
                    ulonglong2 hv = *reinterpret_cast<const ulonglong2*>(hsh + b * HP + k);
#pragma unroll
                    for (int r = 0; r < 16; ++r) {
                        ulonglong2 wv = *reinterpret_cast<const ulonglong2*>(Wsh + r * Hq + k);
                        FMA2(acc2[r], hv.x, wv.x);
                        FMA2(acc2[r], hv.y, wv.y);
                    }
                }
#pragma unroll
                for (int r = 0; r < 16; ++r) {
                    float lo, hi; UNPK2(lo, hi, acc2[r]);
                    part[(wid * 16 + r) * 33 + b] = lo + hi;
                }
            }
            __syncthreads();
        }

        // ---- gates (threads 0..127): reduce partials, nonlinearity ----
        if (tid < 128) {
            float s0 = 0.f, s1 = 0.f, s2 = 0.f, s3 = 0.f;
            if (t > 0) {
#pragma unroll
                for (int w = 0; w < 8; ++w) {
                    s0 += part[(w * 16 + 0 * 4 + gjj) * 33 + gb];
                    s1 += part[(w * 16 + 1 * 4 + gjj) * 33 + gb];
                    s2 += part[(w * 16 + 2 * 4 + gjj) * 33 + gb];
                    s3 += part[(w * 16 + 3 * 4 + gjj) * 33 + gb];
                }
            }
            float iv = s0 + gxv0;
            float fv = s1 + gxv1;
            float gv = s2 + gxv2;
            float ov = s3 + gxv3;
            float si = 1.f / (1.f + __expf(-iv));
            float sf = 1.f / (1.f + __expf(-fv));
            float so = 1.f / (1.f + __expf(-ov));
            float tg = tanhf(gv);
            float c  = sf * csh[tid] + si * tg;
            csh[tid] = c;
            float hn = so * tanhf(c);
            g_h[nxt][gb * Hq + j0 + gjj] = hn;                 // publish h_{t+1}
            out[((size_t)gb * Sq + t) * Hq + j0 + gjj] = hn;

            // prefetch gx for t+1 (hide latency under next wait)
            int tn = (t + 1 < Sq) ? t + 1 : t;
            const float* gp = gx + ((size_t)gb * Sq + tn) * Gq + j0 + gjj;
            gxv0 = gp[0]; gxv1 = gp[Hq]; gxv2 = gp[2 * Hq]; gxv3 = gp[3 * Hq];

            __threadfence();   // h stores visible before flag
        }
        __syncthreads();

        if (tid == 0)
            g_flags[nxt][cta * 32] = ebase + (unsigned)(t + 1);
    }
}

// ---------------- softmax over sequence axis (per (b,h) column) ---------
__global__ void __launch_bounds__(256) softmax_kernel(
    const float* __restrict__ in, float* __restrict__ probs)
{
    int gw = (blockIdx.x * 256 + threadIdx.x) >> 5;  // 0..16383
    int lane = threadIdx.x & 31;
    int bb = gw >> 9;
    int hh = gw & 511;
    const float* p = in + (size_t)bb * Sq * Hq + hh;
    float v[8];
    float mx = -3.4e38f;
#pragma unroll
    for (int i = 0; i < 8; ++i) {
        v[i] = p[(size_t)(lane + 32 * i) * Hq];
        mx = fmaxf(mx, v[i]);
    }
#pragma unroll
    for (int o = 16; o; o >>= 1) mx = fmaxf(mx, __shfl_xor_sync(0xffffffffu, mx, o));
    float sum = 0.f;
#pragma unroll
    for (int i = 0; i < 8; ++i) { v[i] = __expf(v[i] - mx); sum += v[i]; }
#pragma unroll
    for (int o = 16; o; o >>= 1) sum += __shfl_xor_sync(0xffffffffu, sum, o);
    float inv = 1.f / sum;
    float* q = probs + (size_t)bb * Sq * Hq + hh;
#pragma unroll
    for (int i = 0; i < 8; ++i) q[(size_t)(lane + 32 * i) * Hq] = v[i] * inv;
}

// ---------------- final FC ------------------------------------------------
__global__ void __launch_bounds__(256) fc_kernel(
    const float* __restrict__ probs, const float* __restrict__ Wfc,
    const float* __restrict__ bfc, float* __restrict__ out)
{
    int gw = (blockIdx.x * 256 + threadIdx.x) >> 5;  // (b,s)
    int lane = threadIdx.x & 31;
    const float* p = probs + (size_t)gw * Hq;
    float a0 = 0.f, a1 = 0.f, a2 = 0.f, a3 = 0.f;
    for (int k = lane; k < Hq; k += 32) {
        float pv = p[k];
        a0 += pv * Wfc[k];
        a1 += pv * Wfc[Hq + k];
        a2 += pv * Wfc[2 * Hq + k];
        a3 += pv * Wfc[3 * Hq + k];
    }
#pragma unroll
    for (int o = 16; o; o >>= 1) {
        a0 += __shfl_xor_sync(0xffffffffu, a0, o);
        a1 += __shfl_xor_sync(0xffffffffu, a1, o);
        a2 += __shfl_xor_sync(0xffffffffu, a2, o);
        a3 += __shfl_xor_sync(0xffffffffu, a3, o);
    }
    if (lane == 0) {
        float4 r;
        r.x = a0 + bfc[0]; r.y = a1 + bfc[1];
        r.z = a2 + bfc[2]; r.w = a3 + bfc[3];
        *reinterpret_cast<float4*>(out + (size_t)gw * 4) = r;
    }
}

// ---------------- launcher -----------------------------------------------
extern "C" void kernel_launch(void* const* d_in, const int* in_sizes, int n_in,
                              void* d_out, int out_size)
{
    const float* x    = (const float*)d_in[0];  // [32,256,256]
    const float* Wih0 = (const float*)d_in[1];  // [2048,256]
    const float* WihR = (const float*)d_in[2];  // [3,2048,512]
    const float* Whh  = (const float*)d_in[3];  // [4,2048,512]
    const float* bih  = (const float*)d_in[4];  // [4,2048]
    const float* bhh  = (const float*)d_in[5];  // [4,2048]
    const float* Wfc  = (const float*)d_in[6];  // [4,512]
    const float* bfc  = (const float*)d_in[7];  // [4]
    float* out = (float*)d_out;                 // [32,256,4] f32

    float *gx, *io0, *io1;
    cudaGetSymbolAddress((void**)&gx,  g_gx);
    cudaGetSymbolAddress((void**)&io0, g_io0);
    cudaGetSymbolAddress((void**)&io1, g_io1);

    cudaFuncSetAttribute(lstm_scan_kernel,
                         cudaFuncAttributeMaxDynamicSharedMemorySize,
                         SCAN_SMEM_BYTES);

    const float* lin[4]  = {x, io0, io1, io0};
    float*       lout[4] = {io0, io1, io0, io1};

    for (int l = 0; l < 4; ++l) {
        int K = (l == 0) ? Eq : Hq;
        const float* Wih = (l == 0) ? Wih0 : (WihR + (size_t)(l - 1) * Gq * Hq);
        gemm_kernel<<<dim3(Gq / 128, M_TOT / 128), 256>>>(
            lin[l], Wih, bih + (size_t)l * Gq, bhh + (size_t)l * Gq, gx, K);
        lstm_scan_kernel<<<SCAN_NCTA, SCAN_TPB, SCAN_SMEM_BYTES>>>(
            gx, Whh + (size_t)l * Gq * Hq, lout[l], (unsigned)(l * Sq));
    }

    softmax_kernel<<<2048, 256>>>(io1, gx);
    fc_kernel<<<1024, 256>>>(gx, Wfc, bfc, out);
}

// round 5
// speedup vs baseline: 1.7379x; 1.0300x over previous
#include <cuda_runtime.h>
#include <cstdint>

#define Bq 32
#define Sq 256
#define Eq 256
#define Hq 512
#define Gq 2048          // 4*H
#define M_TOT (Bq * Sq)  // 8192

#define SCAN_NCTA 128
#define SCAN_TPB  256
#define HP 132           // hsh row pad (floats): conflict-free LDS.128 per-b rows

// SMEM: Wsh 16*512 | hsh 32*132 | part 8*16*33 | csh 128
#define SCAN_SMEM_FLOATS (16 * Hq + Bq * HP + 8 * 16 * 33 + 128)
#define SCAN_SMEM_BYTES  (SCAN_SMEM_FLOATS * 4)

typedef unsigned long long ull;

// packed f32x2 helpers (sm_103a FFMA2 path)
#define FMA2(acc, a, b) \
    asm("fma.rn.f32x2 %0, %1, %2, %0;" : "+l"(acc) : "l"(a), "l"(b))
#define DUP2(d, s) \
    asm("mov.b64 %0, {%1, %1};" : "=l"(d) : "f"(s))
#define UNPK2(lo, hi, v) \
    asm("mov.b64 {%0, %1}, %2;" : "=f"(lo), "=f"(hi) : "l"(v))

// ---------------- device scratch (static, no allocation) ----------------
__device__ float g_gx[M_TOT * Gq];       // 64MB gate pre-activations; reused as probs
__device__ float g_io0[M_TOT * Hq];      // 16MB layer ping
__device__ float g_io1[M_TOT * Hq];      // 16MB layer pong
__device__ float g_h[2][Bq * Hq];        // recurrent h double buffer, [b][k]
__device__ unsigned g_flags[2][SCAN_NCTA * 32];  // per-CTA 128B-padded flags

// ---------------- input GEMM: C[m][g] = A[m][:]·W[g][:] + bih[g]+bhh[g] --
__global__ void __launch_bounds__(256) gemm_kernel(
    const float* __restrict__ A, const float* __restrict__ W,
    const float* __restrict__ bih, const float* __restrict__ bhh,
    float* __restrict__ C, int K)
{
    __shared__ float As[8][128];
    __shared__ float Bs[8][128];
    const int tid = threadIdx.x;
    const int m0 = blockIdx.y * 128;
    const int n0 = blockIdx.x * 128;
    const int lr = tid >> 1;
    const int lk = (tid & 1) * 4;
    const int tx = tid & 15;
    const int ty = tid >> 4;

    ull acc2[8][4];
#pragma unroll
    for (int i = 0; i < 8; ++i)
#pragma unroll
        for (int j = 0; j < 4; ++j) acc2[i][j] = 0ull;

    const float* Ap = A + (size_t)(m0 + lr) * K + lk;
    const float* Wp = W + (size_t)(n0 + lr) * K + lk;
    float4 pa = *reinterpret_cast<const float4*>(Ap);
    float4 pb = *reinterpret_cast<const float4*>(Wp);

    for (int k0 = 0; k0 < K; k0 += 8) {
        As[lk + 0][lr] = pa.x; As[lk + 1][lr] = pa.y;
        As[lk + 2][lr] = pa.z; As[lk + 3][lr] = pa.w;
        Bs[lk + 0][lr] = pb.x; Bs[lk + 1][lr] = pb.y;
        Bs[lk + 2][lr] = pb.z; Bs[lk + 3][lr] = pb.w;
        __syncthreads();
        if (k0 + 8 < K) {
            pa = *reinterpret_cast<const float4*>(Ap + k0 + 8);
            pb = *reinterpret_cast<const float4*>(Wp + k0 + 8);
        }
#pragma unroll
        for (int kk = 0; kk < 8; ++kk) {
            float4 a0 = *reinterpret_cast<const float4*>(&As[kk][ty * 4]);
            float4 a1 = *reinterpret_cast<const float4*>(&As[kk][64 + ty * 4]);
            ulonglong2 bb0 = *reinterpret_cast<const ulonglong2*>(&Bs[kk][tx * 4]);
            ulonglong2 bb1 = *reinterpret_cast<const ulonglong2*>(&Bs[kk][64 + tx * 4]);
            float am[8] = {a0.x, a0.y, a0.z, a0.w, a1.x, a1.y, a1.z, a1.w};
            ull bp0 = bb0.x, bp1 = bb0.y, bp2 = bb1.x, bp3 = bb1.y;
#pragma unroll
            for (int i = 0; i < 8; ++i) {
                ull a2; DUP2(a2, am[i]);
                FMA2(acc2[i][0], a2, bp0);
                FMA2(acc2[i][1], a2, bp1);
                FMA2(acc2[i][2], a2, bp2);
                FMA2(acc2[i][3], a2, bp3);
            }
        }
        __syncthreads();
    }

    float acc[8][8];
#pragma unroll
    for (int i = 0; i < 8; ++i)
#pragma unroll
        for (int j = 0; j < 4; ++j)
            UNPK2(acc[i][2 * j], acc[i][2 * j + 1], acc2[i][j]);

    const int nc0 = n0 + tx * 4;
    const int nc1 = n0 + 64 + tx * 4;
    float bs0[4], bs1[4];
#pragma unroll
    for (int j = 0; j < 4; ++j) {
        bs0[j] = bih[nc0 + j] + bhh[nc0 + j];
        bs1[j] = bih[nc1 + j] + bhh[nc1 + j];
    }
#pragma unroll
    for (int i = 0; i < 8; ++i) {
        int m = m0 + ((i < 4) ? (ty * 4 + i) : (64 + ty * 4 + i - 4));
        float4 v0, v1;
        v0.x = acc[i][0] + bs0[0]; v0.y = acc[i][1] + bs0[1];
        v0.z = acc[i][2] + bs0[2]; v0.w = acc[i][3] + bs0[3];
        v1.x = acc[i][4] + bs1[0]; v1.y = acc[i][5] + bs1[1];
        v1.z = acc[i][6] + bs1[2]; v1.w = acc[i][7] + bs1[3];
        *reinterpret_cast<float4*>(C + (size_t)m * Gq + nc0) = v0;
        *reinterpret_cast<float4*>(C + (size_t)m * Gq + nc1) = v1;
    }
}

// ---------------- persistent recurrent scan (one launch per layer) ------
// 128 CTAs co-resident (<=148 SMs). CTA owns 4 h-cols (16 gate rows).
// Sync via per-CTA padded flags; publish = ONE st.release.gpu per CTA.
__global__ void __launch_bounds__(SCAN_TPB) lstm_scan_kernel(
    const float* __restrict__ gx,   // [b][s][2048]
    const float* __restrict__ Whh,  // [2048][512] this layer
    float* __restrict__ out,        // [b][s][512]
    unsigned ebase)                 // layer * Sq (epoch base)
{
    extern __shared__ float sm[];
    float* Wsh  = sm;                      // 16 * 512
    float* hsh  = Wsh + 16 * Hq;           // 32 * HP
    float* part = hsh + Bq * HP;           // 8 * 16 * 33
    float* csh  = part + 8 * 16 * 33;      // 128

    const int tid  = threadIdx.x;
    const int cta  = blockIdx.x;
    const int j0   = cta * 4;
    const int wid  = tid >> 5;
    const int lane = tid & 31;

    // load this CTA's 16 Whh rows: local r -> global row (r>>2)*512 + j0 + (r&3)
    for (int i = tid; i < 16 * (Hq / 4); i += SCAN_TPB) {
        int r  = i / (Hq / 4);
        int k4 = i % (Hq / 4);
        int grow = (r >> 2) * Hq + j0 + (r & 3);
        reinterpret_cast<float4*>(Wsh + r * Hq)[k4] =
            reinterpret_cast<const float4*>(Whh + (size_t)grow * Hq)[k4];
    }
    if (tid < 128) csh[tid] = 0.f;
    __syncthreads();

    const int gb  = tid & 31;          // gate-thread batch
    const int gjj = (tid >> 5) & 3;    // gate-thread column (tid<128)

    // prefetch gx for t=0
    float gxv0 = 0.f, gxv1 = 0.f, gxv2 = 0.f, gxv3 = 0.f;
    if (tid < 128) {
        const float* gp = gx + (size_t)gb * Sq * Gq + j0 + gjj;
        gxv0 = gp[0]; gxv1 = gp[Hq]; gxv2 = gp[2 * Hq]; gxv3 = gp[3 * Hq];
    }

    for (int t = 0; t < Sq; ++t) {
        const int cur = t & 1, nxt = cur ^ 1;

        if (t > 0) {
            // ---- wait: all CTAs published h_t (flags[cur][*] == ebase+t) ----
            if (wid == 7) {
                unsigned target = ebase + (unsigned)t;
                volatile unsigned* f = (volatile unsigned*)&g_flags[cur][0];
                bool done = false;
                do {
                    bool ok = true;
#pragma unroll
                    for (int i = 0; i < 4; ++i)
                        ok &= (f[(lane * 4 + i) * 32] == target);
                    done = __all_sync(0xffffffffu, ok);
                } while (!done);
                __threadfence();   // acquire: CCTL.IVALL -> fresh g_h in L1
            }
            __syncthreads();

            // ---- stage h_t: g_h[cur] ([b][k]) -> hsh[b][k] (pad HP) ----
            const float4* hsrc = reinterpret_cast<const float4*>(g_h[cur]);
#pragma unroll
            for (int i = 0; i < (Bq * Hq / 4) / SCAN_TPB; ++i) {
                int q  = i * SCAN_TPB + tid;
                int bb = q >> 7;       // /128 float4 per b-row
                int kq = q & 127;
                *reinterpret_cast<float4*>(hsh + bb * HP + kq * 4) = hsrc[q];
            }
            __syncthreads();

            // ---- dot: warp wid -> k chunk [wid*64, wid*64+64), all 16 rows ----
            {
                const int kbase = wid * 64;
                const int b = lane;
                ull acc2[16];
#pragma unroll
                for (int r = 0; r < 16; ++r) acc2[r] = 0ull;
#pragma unroll 4
                for (int k4 = 0; k4 < 16; ++k4) {
                    int k = kbase + k4 * 4;
                    ulonglong2 hv = *reinterpret_cast<const ulonglong2*>(hsh + b * HP + k);
#pragma unroll
                    for (int r = 0; r < 16; ++r) {
                        ulonglong2 wv = *reinterpret_cast<const ulonglong2*>(Wsh + r * Hq + k);
                        FMA2(acc2[r], hv.x, wv.x);
                        FMA2(acc2[r], hv.y, wv.y);
                    }
                }
#pragma unroll
                for (int r = 0; r < 16; ++r) {
                    float lo, hi; UNPK2(lo, hi, acc2[r]);
                    part[(wid * 16 + r) * 33 + b] = lo + hi;
                }
            }
            __syncthreads();
        }

        // ---- gates (threads 0..127): reduce partials, nonlinearity ----
        if (tid < 128) {
            float s0 = 0.f, s1 = 0.f, s2 = 0.f, s3 = 0.f;
            if (t > 0) {
#pragma unroll
                for (int w = 0; w < 8; ++w) {
                    s0 += part[(w * 16 + 0 * 4 + gjj) * 33 + gb];
                    s1 += part[(w * 16 + 1 * 4 + gjj) * 33 + gb];
                    s2 += part[(w * 16 + 2 * 4 + gjj) * 33 + gb];
                    s3 += part[(w * 16 + 3 * 4 + gjj) * 33 + gb];
                }
            }
            float iv = s0 + gxv0;
            float fv = s1 + gxv1;
            float gv = s2 + gxv2;
            float ov = s3 + gxv3;
            float si = 1.f / (1.f + __expf(-iv));
            float sf = 1.f / (1.f + __expf(-fv));
            float so = 1.f / (1.f + __expf(-ov));
            float tg = tanhf(gv);
            float c  = sf * csh[tid] + si * tg;
            csh[tid] = c;
            float hn = so * tanhf(c);
            g_h[nxt][gb * Hq + j0 + gjj] = hn;                 // publish h_{t+1}
            out[((size_t)gb * Sq + t) * Hq + j0 + gjj] = hn;

            // prefetch gx for t+1 (hide latency under next wait)
            int tn = (t + 1 < Sq) ? t + 1 : t;
            const float* gp = gx + ((size_t)gb * Sq + tn) * Gq + j0 + gjj;
            gxv0 = gp[0]; gxv1 = gp[Hq]; gxv2 = gp[2 * Hq]; gxv3 = gp[3 * Hq];
        }
        __syncthreads();   // all h stores happen-before tid0's release store

        if (tid == 0) {
            unsigned val = ebase + (unsigned)(t + 1);
            asm volatile("st.release.gpu.global.u32 [%0], %1;"
                         :: "l"(&g_flags[nxt][cta * 32]), "r"(val) : "memory");
        }
    }
}

// ---------------- softmax over sequence axis (per (b,h) column) ---------
__global__ void __launch_bounds__(256) softmax_kernel(
    const float* __restrict__ in, float* __restrict__ probs)
{
    int gw = (blockIdx.x * 256 + threadIdx.x) >> 5;  // 0..16383
    int lane = threadIdx.x & 31;
    int bb = gw >> 9;
    int hh = gw & 511;
    const float* p = in + (size_t)bb * Sq * Hq + hh;
    float v[8];
    float mx = -3.4e38f;
#pragma unroll
    for (int i = 0; i < 8; ++i) {
        v[i] = p[(size_t)(lane + 32 * i) * Hq];
        mx = fmaxf(mx, v[i]);
    }
#pragma unroll
    for (int o = 16; o; o >>= 1) mx = fmaxf(mx, __shfl_xor_sync(0xffffffffu, mx, o));
    float sum = 0.f;
#pragma unroll
    for (int i = 0; i < 8; ++i) { v[i] = __expf(v[i] - mx); sum += v[i]; }
#pragma unroll
    for (int o = 16; o; o >>= 1) sum += __shfl_xor_sync(0xffffffffu, sum, o);
    float inv = 1.f / sum;
    float* q = probs + (size_t)bb * Sq * Hq + hh;
#pragma unroll
    for (int i = 0; i < 8; ++i) q[(size_t)(lane + 32 * i) * Hq] = v[i] * inv;
}

// ---------------- final FC ------------------------------------------------
__global__ void __launch_bounds__(256) fc_kernel(
    const float* __restrict__ probs, const float* __restrict__ Wfc,
    const float* __restrict__ bfc, float* __restrict__ out)
{
    int gw = (blockIdx.x * 256 + threadIdx.x) >> 5;  // (b,s)
    int lane = threadIdx.x & 31;
    const float* p = probs + (size_t)gw * Hq;
    float a0 = 0.f, a1 = 0.f, a2 = 0.f, a3 = 0.f;
    for (int k = lane; k < Hq; k += 32) {
        float pv = p[k];
        a0 += pv * Wfc[k];
        a1 += pv * Wfc[Hq + k];
        a2 += pv * Wfc[2 * Hq + k];
        a3 += pv * Wfc[3 * Hq + k];
    }
#pragma unroll
    for (int o = 16; o; o >>= 1) {
        a0 += __shfl_xor_sync(0xffffffffu, a0, o);
        a1 += __shfl_xor_sync(0xffffffffu, a1, o);
        a2 += __shfl_xor_sync(0xffffffffu, a2, o);
        a3 += __shfl_xor_sync(0xffffffffu, a3, o);
    }
    if (lane == 0) {
        float4 r;
        r.x = a0 + bfc[0]; r.y = a1 + bfc[1];
        r.z = a2 + bfc[2]; r.w = a3 + bfc[3];
        *reinterpret_cast<float4*>(out + (size_t)gw * 4) = r;
    }
}

// ---------------- launcher -----------------------------------------------
extern "C" void kernel_launch(void* const* d_in, const int* in_sizes, int n_in,
                              void* d_out, int out_size)
{
    const float* x    = (const float*)d_in[0];  // [32,256,256]
    const float* Wih0 = (const float*)d_in[1];  // [2048,256]
    const float* WihR = (const float*)d_in[2];  // [3,2048,512]
    const float* Whh  = (const float*)d_in[3];  // [4,2048,512]
    const float* bih  = (const float*)d_in[4];  // [4,2048]
    const float* bhh  = (const float*)d_in[5];  // [4,2048]
    const float* Wfc  = (const float*)d_in[6];  // [4,512]
    const float* bfc  = (const float*)d_in[7];  // [4]
    float* out = (float*)d_out;                 // [32,256,4] f32

    float *gx, *io0, *io1;
    cudaGetSymbolAddress((void**)&gx,  g_gx);
    cudaGetSymbolAddress((void**)&io0, g_io0);
    cudaGetSymbolAddress((void**)&io1, g_io1);

    cudaFuncSetAttribute(lstm_scan_kernel,
                         cudaFuncAttributeMaxDynamicSharedMemorySize,
                         SCAN_SMEM_BYTES);

    const float* lin[4]  = {x, io0, io1, io0};
    float*       lout[4] = {io0, io1, io0, io1};

    for (int l = 0; l < 4; ++l) {
        int K = (l == 0) ? Eq : Hq;
        const float* Wih = (l == 0) ? Wih0 : (WihR + (size_t)(l - 1) * Gq * Hq);
        gemm_kernel<<<dim3(Gq / 128, M_TOT / 128), 256>>>(
            lin[l], Wih, bih + (size_t)l * Gq, bhh + (size_t)l * Gq, gx, K);
        lstm_scan_kernel<<<SCAN_NCTA, SCAN_TPB, SCAN_SMEM_BYTES>>>(
            gx, Whh + (size_t)l * Gq * Hq, lout[l], (unsigned)(l * Sq));
    }

    softmax_kernel<<<2048, 256>>>(io1, gx);
    fc_kernel<<<1024, 256>>>(gx, Wfc, bfc, out);
}

// round 6
// speedup vs baseline: 2.1248x; 1.2226x over previous
#include <cuda_runtime.h>
#include <cstdint>

#define Bq 32
#define Sq 256
#define Eq 256
#define Hq 512
#define Gq 2048          // 4*H
#define M_TOT (Bq * Sq)  // 8192

#define SCAN_NCTA 128
#define SCAN_TPB  256
#define NGROUP 4
#define GCTAS  32        // CTAs per group
#define GB     8         // batch elems per group
#define HP 132           // hsh row pad (floats)

// SMEM: Wsh 64*512 | hsh 8*132 | part 8*64*9 | csh 128
#define SCAN_SMEM_FLOATS (64 * Hq + GB * HP + 8 * 64 * 9 + 128)
#define SCAN_SMEM_BYTES  (SCAN_SMEM_FLOATS * 4)

typedef unsigned long long ull;

#define FMA2(acc, a, b) \
    asm("fma.rn.f32x2 %0, %1, %2, %0;" : "+l"(acc) : "l"(a), "l"(b))
#define DUP2(d, s) \
    asm("mov.b64 %0, {%1, %1};" : "=l"(d) : "f"(s))
#define UNPK2(lo, hi, v) \
    asm("mov.b64 {%0, %1}, %2;" : "=f"(lo), "=f"(hi) : "l"(v))

// ---------------- device scratch (static, no allocation) ----------------
__device__ float g_gx[M_TOT * Gq];       // 64MB gate pre-activations; reused as probs
__device__ float g_io0[M_TOT * Hq];      // 16MB layer ping
__device__ float g_io1[M_TOT * Hq];      // 16MB layer pong
__device__ float g_h[2][Bq * Hq];        // recurrent h double buffer, [b][k]
__device__ unsigned g_flags[2][SCAN_NCTA * 32];  // per-CTA 128B-padded flags

// ---------------- input GEMM: C[m][g] = A[m][:]·W[g][:] + bih[g]+bhh[g] --
__global__ void __launch_bounds__(256) gemm_kernel(
    const float* __restrict__ A, const float* __restrict__ W,
    const float* __restrict__ bih, const float* __restrict__ bhh,
    float* __restrict__ C, int K)
{
    __shared__ float As[8][128];
    __shared__ float Bs[8][128];
    const int tid = threadIdx.x;
    const int m0 = blockIdx.y * 128;
    const int n0 = blockIdx.x * 128;
    const int lr = tid >> 1;
    const int lk = (tid & 1) * 4;
    const int tx = tid & 15;
    const int ty = tid >> 4;

    ull acc2[8][4];
#pragma unroll
    for (int i = 0; i < 8; ++i)
#pragma unroll
        for (int j = 0; j < 4; ++j) acc2[i][j] = 0ull;

    const float* Ap = A + (size_t)(m0 + lr) * K + lk;
    const float* Wp = W + (size_t)(n0 + lr) * K + lk;
    float4 pa = *reinterpret_cast<const float4*>(Ap);
    float4 pb = *reinterpret_cast<const float4*>(Wp);

    for (int k0 = 0; k0 < K; k0 += 8) {
        As[lk + 0][lr] = pa.x; As[lk + 1][lr] = pa.y;
        As[lk + 2][lr] = pa.z; As[lk + 3][lr] = pa.w;
        Bs[lk + 0][lr] = pb.x; Bs[lk + 1][lr] = pb.y;
        Bs[lk + 2][lr] = pb.z; Bs[lk + 3][lr] = pb.w;
        __syncthreads();
        if (k0 + 8 < K) {
            pa = *reinterpret_cast<const float4*>(Ap + k0 + 8);
            pb = *reinterpret_cast<const float4*>(Wp + k0 + 8);
        }
#pragma unroll
        for (int kk = 0; kk < 8; ++kk) {
            float4 a0 = *reinterpret_cast<const float4*>(&As[kk][ty * 4]);
            float4 a1 = *reinterpret_cast<const float4*>(&As[kk][64 + ty * 4]);
            ulonglong2 bb0 = *reinterpret_cast<const ulonglong2*>(&Bs[kk][tx * 4]);
            ulonglong2 bb1 = *reinterpret_cast<const ulonglong2*>(&Bs[kk][64 + tx * 4]);
            float am[8] = {a0.x, a0.y, a0.z, a0.w, a1.x, a1.y, a1.z, a1.w};
            ull bp0 = bb0.x, bp1 = bb0.y, bp2 = bb1.x, bp3 = bb1.y;
#pragma unroll
            for (int i = 0; i < 8; ++i) {
                ull a2; DUP2(a2, am[i]);
                FMA2(acc2[i][0], a2, bp0);
                FMA2(acc2[i][1], a2, bp1);
                FMA2(acc2[i][2], a2, bp2);
                FMA2(acc2[i][3], a2, bp3);
            }
        }
        __syncthreads();
    }

    float acc[8][8];
#pragma unroll
    for (int i = 0; i < 8; ++i)
#pragma unroll
        for (int j = 0; j < 4; ++j)
            UNPK2(acc[i][2 * j], acc[i][2 * j + 1], acc2[i][j]);

    const int nc0 = n0 + tx * 4;
    const int nc1 = n0 + 64 + tx * 4;
    float bs0[4], bs1[4];
#pragma unroll
    for (int j = 0; j < 4; ++j) {
        bs0[j] = bih[nc0 + j] + bhh[nc0 + j];
        bs1[j] = bih[nc1 + j] + bhh[nc1 + j];
    }
#pragma unroll
    for (int i = 0; i < 8; ++i) {
        int m = m0 + ((i < 4) ? (ty * 4 + i) : (64 + ty * 4 + i - 4));
        float4 v0, v1;
        v0.x = acc[i][0] + bs0[0]; v0.y = acc[i][1] + bs0[1];
        v0.z = acc[i][2] + bs0[2]; v0.w = acc[i][3] + bs0[3];
        v1.x = acc[i][4] + bs1[0]; v1.y = acc[i][5] + bs1[1];
        v1.z = acc[i][6] + bs1[2]; v1.w = acc[i][7] + bs1[3];
        *reinterpret_cast<float4*>(C + (size_t)m * Gq + nc0) = v0;
        *reinterpret_cast<float4*>(C + (size_t)m * Gq + nc1) = v1;
    }
}

// ---------------- persistent recurrent scan: 4 groups x 32 CTAs ----------
// Group g handles batch b in [g*8, g*8+8). CTA owns 16 h-cols (64 gate rows,
// 128KB Whh in SMEM). Sync only WITHIN a group (32 flags).
__global__ void __launch_bounds__(SCAN_TPB) lstm_scan_kernel(
    const float* __restrict__ gx,   // [b][s][2048]
    const float* __restrict__ Whh,  // [2048][512] this layer
    float* __restrict__ out,        // [b][s][512]
    unsigned ebase)                 // layer * Sq (epoch base)
{
    extern __shared__ float sm[];
    float* Wsh  = sm;                      // 64 * 512
    float* hsh  = Wsh + 64 * Hq;           // 8 * HP
    float* part = hsh + GB * HP;           // 8 * 64 * 9
    float* csh  = part + 8 * 64 * 9;       // 128

    const int tid   = threadIdx.x;
    const int cta   = blockIdx.x;
    const int group = cta >> 5;            // 0..3
    const int cidx  = cta & 31;            // 0..31 within group
    const int j0    = cidx * 16;           // 16 h-cols owned
    const int b0    = group * GB;          // batch base
    const int wid   = tid >> 5;
    const int lane  = tid & 31;

    // zero OWN flag slots (kills cross-replay ABA; stale 0 never matches)
    if (tid == 0) {
        g_flags[0][cta * 32] = 0u;
        g_flags[1][cta * 32] = 0u;
    }

    // load 64 Whh rows: local rl -> global row (rl>>4)*512 + j0 + (rl&15)
    for (int i = tid; i < 64 * (Hq / 4); i += SCAN_TPB) {
        int rl = i >> 7;            // /128 float4 per row
        int k4 = i & 127;
        int grow = (rl >> 4) * Hq + j0 + (rl & 15);
        reinterpret_cast<float4*>(Wsh + rl * Hq)[k4] =
            reinterpret_cast<const float4*>(Whh + (size_t)grow * Hq)[k4];
    }
    if (tid < 128) csh[tid] = 0.f;
    __syncthreads();

    const int bl = tid & 7;            // gate-thread local batch (tid<128)
    const int jj = (tid >> 3) & 15;    // gate-thread h-col

    // prefetch gx for t=0
    float gxv0 = 0.f, gxv1 = 0.f, gxv2 = 0.f, gxv3 = 0.f;
    if (tid < 128) {
        const float* gp = gx + (size_t)(b0 + bl) * Sq * Gq + j0 + jj;
        gxv0 = gp[0]; gxv1 = gp[Hq]; gxv2 = gp[2 * Hq]; gxv3 = gp[3 * Hq];
    }

    const int drq = lane >> 3;         // dot: k-stagger / row-quad (0..3)
    const int dbl = lane & 7;          // dot: local batch

    for (int t = 0; t < Sq; ++t) {
        const int cur = t & 1, nxt = cur ^ 1;

        if (t > 0) {
            // ---- wait: this group's 32 CTAs published h_t ----
            if (wid == 0) {
                unsigned target = ebase + (unsigned)t;
                const unsigned* f = &g_flags[cur][(group * 32 + lane) * 32];
                unsigned v;
                do {
                    asm volatile("ld.relaxed.gpu.global.u32 %0, [%1];"
                                 : "=r"(v) : "l"(f));
                } while (!__all_sync(0xffffffffu, v == target));
            }
            __syncthreads();

            // ---- stage h_t slice (8 b x 512) via ld.cg (L2-direct) ----
            {
                const float4* hsrc =
                    reinterpret_cast<const float4*>(g_h[cur] + (size_t)b0 * Hq);
                int q  = tid;                 // 1024 float4 total, 4 per thread
#pragma unroll
                for (int i = 0; i < 4; ++i, q += SCAN_TPB) {
                    int bb = q >> 7;
                    int kq = q & 127;
                    float4 v = __ldcg(hsrc + q);
                    *reinterpret_cast<float4*>(hsh + bb * HP + kq * 4) = v;
                }
            }
            __syncthreads();

            // ---- dot: warp w -> k-chunk [w*64,w*64+64); lane=(rq,bl) ----
            {
                const int kw = wid * 64;
                ull acc2[16];
#pragma unroll
                for (int r = 0; r < 16; ++r) acc2[r] = 0ull;
#pragma unroll 4
                for (int i = 0; i < 16; ++i) {
                    int k = kw + (((i + drq) * 4) & 63);   // rq-stagger: bank-free W
                    ulonglong2 hv =
                        *reinterpret_cast<const ulonglong2*>(hsh + dbl * HP + k);
#pragma unroll
                    for (int rr = 0; rr < 16; ++rr) {
                        const ulonglong2 wv = *reinterpret_cast<const ulonglong2*>(
                            Wsh + (drq * 16 + rr) * Hq + k);
                        FMA2(acc2[rr], hv.x, wv.x);
                        FMA2(acc2[rr], hv.y, wv.y);
                    }
                }
#pragma unroll
                for (int rr = 0; rr < 16; ++rr) {
                    float lo, hi; UNPK2(lo, hi, acc2[rr]);
                    part[(wid * 64 + drq * 16 + rr) * 9 + dbl] = lo + hi;
                }
            }
            __syncthreads();
        }

        // ---- gates (threads 0..127): 16 cols x 8 b ----
        if (tid < 128) {
            float s0 = 0.f, s1 = 0.f, s2 = 0.f, s3 = 0.f;
            if (t > 0) {
#pragma unroll
                for (int w = 0; w < 8; ++w) {
                    s0 += part[(w * 64 + 0 * 16 + jj) * 9 + bl];
                    s1 += part[(w * 64 + 1 * 16 + jj) * 9 + bl];
                    s2 += part[(w * 64 + 2 * 16 + jj) * 9 + bl];
                    s3 += part[(w * 64 + 3 * 16 + jj) * 9 + bl];
                }
            }
            float iv = s0 + gxv0;
            float fv = s1 + gxv1;
            float gv = s2 + gxv2;
            float ov = s3 + gxv3;
            float si = 1.f / (1.f + __expf(-iv));
            float sf = 1.f / (1.f + __expf(-fv));
            float so = 1.f / (1.f + __expf(-ov));
            float tg = tanhf(gv);
            float c  = sf * csh[tid] + si * tg;
            csh[tid] = c;
            float hn = so * tanhf(c);
            int bglob = b0 + bl;
            g_h[nxt][(size_t)bglob * Hq + j0 + jj] = hn;
            out[((size_t)bglob * Sq + t) * Hq + j0 + jj] = hn;

            // prefetch gx for t+1 (hides DRAM latency under next wait)
            int tn = (t + 1 < Sq) ? t + 1 : t;
            const float* gp = gx + ((size_t)bglob * Sq + tn) * Gq + j0 + jj;
            gxv0 = gp[0]; gxv1 = gp[Hq]; gxv2 = gp[2 * Hq]; gxv3 = gp[3 * Hq];
        }
        __syncthreads();   // all h stores precede the publish

        if (tid == 0) {
            unsigned val = ebase + (unsigned)(t + 1);
            asm volatile("membar.gl;" ::: "memory");   // drain SM store queue
            asm volatile("st.release.gpu.global.u32 [%0], %1;"
                         :: "l"(&g_flags[nxt][cta * 32]), "r"(val) : "memory");
        }
    }
}

// ---------------- softmax over sequence axis (per (b,h) column) ---------
__global__ void __launch_bounds__(256) softmax_kernel(
    const float* __restrict__ in, float* __restrict__ probs)
{
    int gw = (blockIdx.x * 256 + threadIdx.x) >> 5;
    int lane = threadIdx.x & 31;
    int bb = gw >> 9;
    int hh = gw & 511;
    const float* p = in + (size_t)bb * Sq * Hq + hh;
    float v[8];
    float mx = -3.4e38f;
#pragma unroll
    for (int i = 0; i < 8; ++i) {
        v[i] = p[(size_t)(lane + 32 * i) * Hq];
        mx = fmaxf(mx, v[i]);
    }
#pragma unroll
    for (int o = 16; o; o >>= 1) mx = fmaxf(mx, __shfl_xor_sync(0xffffffffu, mx, o));
    float sum = 0.f;
#pragma unroll
    for (int i = 0; i < 8; ++i) { v[i] = __expf(v[i] - mx); sum += v[i]; }
#pragma unroll
    for (int o = 16; o; o >>= 1) sum += __shfl_xor_sync(0xffffffffu, sum, o);
    float inv = 1.f / sum;
    float* q = probs + (size_t)bb * Sq * Hq + hh;
#pragma unroll
    for (int i = 0; i < 8; ++i) q[(size_t)(lane + 32 * i) * Hq] = v[i] * inv;
}

// ---------------- final FC ------------------------------------------------
__global__ void __launch_bounds__(256) fc_kernel(
    const float* __restrict__ probs, const float* __restrict__ Wfc,
    const float* __restrict__ bfc, float* __restrict__ out)
{
    int gw = (blockIdx.x * 256 + threadIdx.x) >> 5;
    int lane = threadIdx.x & 31;
    const float* p = probs + (size_t)gw * Hq;
    float a0 = 0.f, a1 = 0.f, a2 = 0.f, a3 = 0.f;
    for (int k = lane; k < Hq; k += 32) {
        float pv = p[k];
        a0 += pv * Wfc[k];
        a1 += pv * Wfc[Hq + k];
        a2 += pv * Wfc[2 * Hq + k];
        a3 += pv * Wfc[3 * Hq + k];
    }
#pragma unroll
    for (int o = 16; o; o >>= 1) {
        a0 += __shfl_xor_sync(0xffffffffu, a0, o);
        a1 += __shfl_xor_sync(0xffffffffu, a1, o);
        a2 += __shfl_xor_sync(0xffffffffu, a2, o);
        a3 += __shfl_xor_sync(0xffffffffu, a3, o);
    }
    if (lane == 0) {
        float4 r;
        r.x = a0 + bfc[0]; r.y = a1 + bfc[1];
        r.z = a2 + bfc[2]; r.w = a3 + bfc[3];
        *reinterpret_cast<float4*>(out + (size_t)gw * 4) = r;
    }
}

// ---------------- launcher -----------------------------------------------
extern "C" void kernel_launch(void* const* d_in, const int* in_sizes, int n_in,
                              void* d_out, int out_size)
{
    const float* x    = (const float*)d_in[0];
    const float* Wih0 = (const float*)d_in[1];
    const float* WihR = (const float*)d_in[2];
    const float* Whh  = (const float*)d_in[3];
    const float* bih  = (const float*)d_in[4];
    const float* bhh  = (const float*)d_in[5];
    const float* Wfc  = (const float*)d_in[6];
    const float* bfc  = (const float*)d_in[7];
    float* out = (float*)d_out;

    float *gx, *io0, *io1;
    cudaGetSymbolAddress((void**)&gx,  g_gx);
    cudaGetSymbolAddress((void**)&io0, g_io0);
    cudaGetSymbolAddress((void**)&io1, g_io1);

    cudaFuncSetAttribute(lstm_scan_kernel,
                         cudaFuncAttributeMaxDynamicSharedMemorySize,
                         SCAN_SMEM_BYTES);

    const float* lin[4]  = {x, io0, io1, io0};
    float*       lout[4] = {io0, io1, io0, io1};

    for (int l = 0; l < 4; ++l) {
        int K = (l == 0) ? Eq : Hq;
        const float* Wih = (l == 0) ? Wih0 : (WihR + (size_t)(l - 1) * Gq * Hq);
        gemm_kernel<<<dim3(Gq / 128, M_TOT / 128), 256>>>(
            lin[l], Wih, bih + (size_t)l * Gq, bhh + (size_t)l * Gq, gx, K);
        lstm_scan_kernel<<<SCAN_NCTA, SCAN_TPB, SCAN_SMEM_BYTES>>>(
            gx, Whh + (size_t)l * Gq * Hq, lout[l], (unsigned)(l * Sq));
    }

    softmax_kernel<<<2048, 256>>>(io1, gx);
    fc_kernel<<<1024, 256>>>(gx, Wfc, bfc, out);
}

// round 7
// speedup vs baseline: 2.1824x; 1.0271x over previous
#include <cuda_runtime.h>
#include <cstdint>

#define Bq 32
#define Sq 256
#define Eq 256
#define Hq 512
#define Gq 2048          // 4*H
#define M_TOT (Bq * Sq)  // 8192

#define SCAN_NCTA 128
#define SCAN_TPB  256
#define NGROUP 4
#define GCTAS  32        // CTAs per group
#define GB     8         // batch elems per group
#define HP 132           // hsh row pad (floats)

// SMEM: Wsh 64*512 | hsh 8*132 | part 8*64*9 | csh 128
#define SCAN_SMEM_FLOATS (64 * Hq + GB * HP + 8 * 64 * 9 + 128)
#define SCAN_SMEM_BYTES  (SCAN_SMEM_FLOATS * 4)

typedef unsigned long long ull;

#define FMA2(acc, a, b) \
    asm("fma.rn.f32x2 %0, %1, %2, %0;" : "+l"(acc) : "l"(a), "l"(b))
#define DUP2(d, s) \
    asm("mov.b64 %0, {%1, %1};" : "=l"(d) : "f"(s))
#define UNPK2(lo, hi, v) \
    asm("mov.b64 {%0, %1}, %2;" : "=f"(lo), "=f"(hi) : "l"(v))

// ---------------- device scratch (static, no allocation) ----------------
__device__ float g_gx[M_TOT * Gq];       // 64MB gate pre-activations; reused as probs
__device__ float g_io0[M_TOT * Hq];      // 16MB layer ping
__device__ float g_io1[M_TOT * Hq];      // 16MB layer pong
__device__ float g_h[2][Bq * Hq];        // recurrent h double buffer, [b][k]
__device__ unsigned g_flags[2][SCAN_NCTA * 32];  // per-CTA 128B-padded flags

// ---------------- input GEMM: C[m][g] = A[m][:]·W[g][:] + bih[g]+bhh[g] --
__global__ void __launch_bounds__(256) gemm_kernel(
    const float* __restrict__ A, const float* __restrict__ W,
    const float* __restrict__ bih, const float* __restrict__ bhh,
    float* __restrict__ C, int K)
{
    __shared__ float As[8][128];
    __shared__ float Bs[8][128];
    const int tid = threadIdx.x;
    const int m0 = blockIdx.y * 128;
    const int n0 = blockIdx.x * 128;
    const int lr = tid >> 1;
    const int lk = (tid & 1) * 4;
    const int tx = tid & 15;
    const int ty = tid >> 4;

    ull acc2[8][4];
#pragma unroll
    for (int i = 0; i < 8; ++i)
#pragma unroll
        for (int j = 0; j < 4; ++j) acc2[i][j] = 0ull;

    const float* Ap = A + (size_t)(m0 + lr) * K + lk;
    const float* Wp = W + (size_t)(n0 + lr) * K + lk;
    float4 pa = *reinterpret_cast<const float4*>(Ap);
    float4 pb = *reinterpret_cast<const float4*>(Wp);

    for (int k0 = 0; k0 < K; k0 += 8) {
        As[lk + 0][lr] = pa.x; As[lk + 1][lr] = pa.y;
        As[lk + 2][lr] = pa.z; As[lk + 3][lr] = pa.w;
        Bs[lk + 0][lr] = pb.x; Bs[lk + 1][lr] = pb.y;
        Bs[lk + 2][lr] = pb.z; Bs[lk + 3][lr] = pb.w;
        __syncthreads();
        if (k0 + 8 < K) {
            pa = *reinterpret_cast<const float4*>(Ap + k0 + 8);
            pb = *reinterpret_cast<const float4*>(Wp + k0 + 8);
        }
#pragma unroll
        for (int kk = 0; kk < 8; ++kk) {
            float4 a0 = *reinterpret_cast<const float4*>(&As[kk][ty * 4]);
            float4 a1 = *reinterpret_cast<const float4*>(&As[kk][64 + ty * 4]);
            ulonglong2 bb0 = *reinterpret_cast<const ulonglong2*>(&Bs[kk][tx * 4]);
            ulonglong2 bb1 = *reinterpret_cast<const ulonglong2*>(&Bs[kk][64 + tx * 4]);
            float am[8] = {a0.x, a0.y, a0.z, a0.w, a1.x, a1.y, a1.z, a1.w};
            ull bp0 = bb0.x, bp1 = bb0.y, bp2 = bb1.x, bp3 = bb1.y;
#pragma unroll
            for (int i = 0; i < 8; ++i) {
                ull a2; DUP2(a2, am[i]);
                FMA2(acc2[i][0], a2, bp0);
                FMA2(acc2[i][1], a2, bp1);
                FMA2(acc2[i][2], a2, bp2);
                FMA2(acc2[i][3], a2, bp3);
            }
        }
        __syncthreads();
    }

    float acc[8][8];
#pragma unroll
    for (int i = 0; i < 8; ++i)
#pragma unroll
        for (int j = 0; j < 4; ++j)
            UNPK2(acc[i][2 * j], acc[i][2 * j + 1], acc2[i][j]);

    const int nc0 = n0 + tx * 4;
    const int nc1 = n0 + 64 + tx * 4;
    float bs0[4], bs1[4];
#pragma unroll
    for (int j = 0; j < 4; ++j) {
        bs0[j] = bih[nc0 + j] + bhh[nc0 + j];
        bs1[j] = bih[nc1 + j] + bhh[nc1 + j];
    }
#pragma unroll
    for (int i = 0; i < 8; ++i) {
        int m = m0 + ((i < 4) ? (ty * 4 + i) : (64 + ty * 4 + i - 4));
        float4 v0, v1;
        v0.x = acc[i][0] + bs0[0]; v0.y = acc[i][1] + bs0[1];
        v0.z = acc[i][2] + bs0[2]; v0.w = acc[i][3] + bs0[3];
        v1.x = acc[i][4] + bs1[0]; v1.y = acc[i][5] + bs1[1];
        v1.z = acc[i][6] + bs1[2]; v1.w = acc[i][7] + bs1[3];
        *reinterpret_cast<float4*>(C + (size_t)m * Gq + nc0) = v0;
        *reinterpret_cast<float4*>(C + (size_t)m * Gq + nc1) = v1;
    }
}

// ---------------- persistent recurrent scan: 4 groups x 32 CTAs ----------
// Group g handles batch b in [g*8, g*8+8). CTA owns 16 h-cols (64 gate rows,
// 128KB Whh in SMEM). Sync only WITHIN a group (32 flags).
__global__ void __launch_bounds__(SCAN_TPB) lstm_scan_kernel(
    const float* __restrict__ gx,   // [b][s][2048]
    const float* __restrict__ Whh,  // [2048][512] this layer
    float* __restrict__ out,        // [b][s][512]
    unsigned ebase)                 // layer * Sq (epoch base)
{
    extern __shared__ float sm[];
    float* Wsh  = sm;                      // 64 * 512
    float* hsh  = Wsh + 64 * Hq;           // 8 * HP
    float* part = hsh + GB * HP;           // 8 * 64 * 9
    float* csh  = part + 8 * 64 * 9;       // 128

    const int tid   = threadIdx.x;
    const int cta   = blockIdx.x;
    const int group = cta >> 5;            // 0..3
    const int cidx  = cta & 31;            // 0..31 within group
    const int j0    = cidx * 16;           // 16 h-cols owned
    const int b0    = group * GB;          // batch base
    const int wid   = tid >> 5;
    const int lane  = tid & 31;

    // zero OWN flag slots (kills cross-replay ABA; stale 0 never matches)
    if (tid == 0) {
        g_flags[0][cta * 32] = 0u;
        g_flags[1][cta * 32] = 0u;
    }

    // load 64 Whh rows: local rl -> global row (rl>>4)*512 + j0 + (rl&15)
    for (int i = tid; i < 64 * (Hq / 4); i += SCAN_TPB) {
        int rl = i >> 7;            // /128 float4 per row
        int k4 = i & 127;
        int grow = (rl >> 4) * Hq + j0 + (rl & 15);
        reinterpret_cast<float4*>(Wsh + rl * Hq)[k4] =
            reinterpret_cast<const float4*>(Whh + (size_t)grow * Hq)[k4];
    }
    if (tid < 128) csh[tid] = 0.f;
    __syncthreads();

    const int bl = tid & 7;            // gate-thread local batch (tid<128)
    const int jj = (tid >> 3) & 15;    // gate-thread h-col

    // prefetch gx for t=0
    float gxv0 = 0.f, gxv1 = 0.f, gxv2 = 0.f, gxv3 = 0.f;
    if (tid < 128) {
        const float* gp = gx + (size_t)(b0 + bl) * Sq * Gq + j0 + jj;
        gxv0 = gp[0]; gxv1 = gp[Hq]; gxv2 = gp[2 * Hq]; gxv3 = gp[3 * Hq];
    }

    const int drq = lane >> 3;         // dot: k-stagger / row-quad (0..3)
    const int dbl = lane & 7;          // dot: local batch

    for (int t = 0; t < Sq; ++t) {
        const int cur = t & 1, nxt = cur ^ 1;

        if (t > 0) {
            // ---- wait: this group's 32 CTAs published h_t ----
            if (wid == 0) {
                unsigned target = ebase + (unsigned)t;
                const unsigned* f = &g_flags[cur][(group * 32 + lane) * 32];
                unsigned v;
                do {
                    asm volatile("ld.relaxed.gpu.global.u32 %0, [%1];"
                                 : "=r"(v) : "l"(f));
                } while (!__all_sync(0xffffffffu, v == target));
            }
            __syncthreads();

            // ---- stage h_t slice (8 b x 512) via ld.cg (L2-direct) ----
            {
                const float4* hsrc =
                    reinterpret_cast<const float4*>(g_h[cur] + (size_t)b0 * Hq);
                int q  = tid;                 // 1024 float4 total, 4 per thread
#pragma unroll
                for (int i = 0; i < 4; ++i, q += SCAN_TPB) {
                    int bb = q >> 7;
                    int kq = q & 127;
                    float4 v = __ldcg(hsrc + q);
                    *reinterpret_cast<float4*>(hsh + bb * HP + kq * 4) = v;
                }
            }
            __syncthreads();

            // ---- dot: warp w -> k-chunk [w*64,w*64+64); lane=(rq,bl) ----
            {
                const int kw = wid * 64;
                ull acc2[16];
#pragma unroll
                for (int r = 0; r < 16; ++r) acc2[r] = 0ull;
#pragma unroll 4
                for (int i = 0; i < 16; ++i) {
                    int k = kw + (((i + drq) * 4) & 63);   // rq-stagger: bank-free W
                    ulonglong2 hv =
                        *reinterpret_cast<const ulonglong2*>(hsh + dbl * HP + k);
#pragma unroll
                    for (int rr = 0; rr < 16; ++rr) {
                        const ulonglong2 wv = *reinterpret_cast<const ulonglong2*>(
                            Wsh + (drq * 16 + rr) * Hq + k);
                        FMA2(acc2[rr], hv.x, wv.x);
                        FMA2(acc2[rr], hv.y, wv.y);
                    }
                }
#pragma unroll
                for (int rr = 0; rr < 16; ++rr) {
                    float lo, hi; UNPK2(lo, hi, acc2[rr]);
                    part[(wid * 64 + drq * 16 + rr) * 9 + dbl] = lo + hi;
                }
            }
            __syncthreads();
        }

        // ---- gates (threads 0..127): 16 cols x 8 b ----
        if (tid < 128) {
            float s0 = 0.f, s1 = 0.f, s2 = 0.f, s3 = 0.f;
            if (t > 0) {
#pragma unroll
                for (int w = 0; w < 8; ++w) {
                    s0 += part[(w * 64 + 0 * 16 + jj) * 9 + bl];
                    s1 += part[(w * 64 + 1 * 16 + jj) * 9 + bl];
                    s2 += part[(w * 64 + 2 * 16 + jj) * 9 + bl];
                    s3 += part[(w * 64 + 3 * 16 + jj) * 9 + bl];
                }
            }
            float iv = s0 + gxv0;
            float fv = s1 + gxv1;
            float gv = s2 + gxv2;
            float ov = s3 + gxv3;
            float si = 1.f / (1.f + __expf(-iv));
            float sf = 1.f / (1.f + __expf(-fv));
            float so = 1.f / (1.f + __expf(-ov));
            float tg = tanhf(gv);
            float c  = sf * csh[tid] + si * tg;
            csh[tid] = c;
            float hn = so * tanhf(c);
            int bglob = b0 + bl;
            g_h[nxt][(size_t)bglob * Hq + j0 + jj] = hn;
            out[((size_t)bglob * Sq + t) * Hq + j0 + jj] = hn;

            // prefetch gx for t+1 (hides DRAM latency under next wait)
            int tn = (t + 1 < Sq) ? t + 1 : t;
            const float* gp = gx + ((size_t)bglob * Sq + tn) * Gq + j0 + jj;
            gxv0 = gp[0]; gxv1 = gp[Hq]; gxv2 = gp[2 * Hq]; gxv3 = gp[3 * Hq];
        }
        __syncthreads();   // all h stores precede the publish

        if (tid == 0) {
            unsigned val = ebase + (unsigned)(t + 1);
            asm volatile("membar.gl;" ::: "memory");   // drain SM store queue
            asm volatile("st.release.gpu.global.u32 [%0], %1;"
                         :: "l"(&g_flags[nxt][cta * 32]), "r"(val) : "memory");
        }
    }
}

// ---------------- softmax over sequence axis (per (b,h) column) ---------
__global__ void __launch_bounds__(256) softmax_kernel(
    const float* __restrict__ in, float* __restrict__ probs)
{
    int gw = (blockIdx.x * 256 + threadIdx.x) >> 5;
    int lane = threadIdx.x & 31;
    int bb = gw >> 9;
    int hh = gw & 511;
    const float* p = in + (size_t)bb * Sq * Hq + hh;
    float v[8];
    float mx = -3.4e38f;
#pragma unroll
    for (int i = 0; i < 8; ++i) {
        v[i] = p[(size_t)(lane + 32 * i) * Hq];
        mx = fmaxf(mx, v[i]);
    }
#pragma unroll
    for (int o = 16; o; o >>= 1) mx = fmaxf(mx, __shfl_xor_sync(0xffffffffu, mx, o));
    float sum = 0.f;
#pragma unroll
    for (int i = 0; i < 8; ++i) { v[i] = __expf(v[i] - mx); sum += v[i]; }
#pragma unroll
    for (int o = 16; o; o >>= 1) sum += __shfl_xor_sync(0xffffffffu, sum, o);
    float inv = 1.f / sum;
    float* q = probs + (size_t)bb * Sq * Hq + hh;
#pragma unroll
    for (int i = 0; i < 8; ++i) q[(size_t)(lane + 32 * i) * Hq] = v[i] * inv;
}

// ---------------- final FC ------------------------------------------------
__global__ void __launch_bounds__(256) fc_kernel(
    const float* __restrict__ probs, const float* __restrict__ Wfc,
    const float* __restrict__ bfc, float* __restrict__ out)
{
    int gw = (blockIdx.x * 256 + threadIdx.x) >> 5;
    int lane = threadIdx.x & 31;
    const float* p = probs + (size_t)gw * Hq;
    float a0 = 0.f, a1 = 0.f, a2 = 0.f, a3 = 0.f;
    for (int k = lane; k < Hq; k += 32) {
        float pv = p[k];
        a0 += pv * Wfc[k];
        a1 += pv * Wfc[Hq + k];
        a2 += pv * Wfc[2 * Hq + k];
        a3 += pv * Wfc[3 * Hq + k];
    }
#pragma unroll
    for (int o = 16; o; o >>= 1) {
        a0 += __shfl_xor_sync(0xffffffffu, a0, o);
        a1 += __shfl_xor_sync(0xffffffffu, a1, o);
        a2 += __shfl_xor_sync(0xffffffffu, a2, o);
        a3 += __shfl_xor_sync(0xffffffffu, a3, o);
    }
    if (lane == 0) {
        float4 r;
        r.x = a0 + bfc[0]; r.y = a1 + bfc[1];
        r.z = a2 + bfc[2]; r.w = a3 + bfc[3];
        *reinterpret_cast<float4*>(out + (size_t)gw * 4) = r;
    }
}

// ---------------- launcher -----------------------------------------------
extern "C" void kernel_launch(void* const* d_in, const int* in_sizes, int n_in,
                              void* d_out, int out_size)
{
    const float* x    = (const float*)d_in[0];
    const float* Wih0 = (const float*)d_in[1];
    const float* WihR = (const float*)d_in[2];
    const float* Whh  = (const float*)d_in[3];
    const float* bih  = (const float*)d_in[4];
    const float* bhh  = (const float*)d_in[5];
    const float* Wfc  = (const float*)d_in[6];
    const float* bfc  = (const float*)d_in[7];
    float* out = (float*)d_out;

    float *gx, *io0, *io1;
    cudaGetSymbolAddress((void**)&gx,  g_gx);
    cudaGetSymbolAddress((void**)&io0, g_io0);
    cudaGetSymbolAddress((void**)&io1, g_io1);

    cudaFuncSetAttribute(lstm_scan_kernel,
                         cudaFuncAttributeMaxDynamicSharedMemorySize,
                         SCAN_SMEM_BYTES);

    const float* lin[4]  = {x, io0, io1, io0};
    float*       lout[4] = {io0, io1, io0, io1};

    for (int l = 0; l < 4; ++l) {
        int K = (l == 0) ? Eq : Hq;
        const float* Wih = (l == 0) ? Wih0 : (WihR + (size_t)(l - 1) * Gq * Hq);
        gemm_kernel<<<dim3(Gq / 128, M_TOT / 128), 256>>>(
            lin[l], Wih, bih + (size_t)l * Gq, bhh + (size_t)l * Gq, gx, K);
        lstm_scan_kernel<<<SCAN_NCTA, SCAN_TPB, SCAN_SMEM_BYTES>>>(
            gx, Whh + (size_t)l * Gq * Hq, lout[l], (unsigned)(l * Sq));
    }

    softmax_kernel<<<2048, 256>>>(io1, gx);
    fc_kernel<<<1024, 256>>>(gx, Wfc, bfc, out);
}

// round 8
// speedup vs baseline: 2.5422x; 1.1649x over previous
#include <cuda_runtime.h>
#include <cstdint>

#define Bq 32
#define Sq 256
#define Eq 256
#define Hq 512
#define Gq 2048          // 4*H
#define M_TOT (Bq * Sq)  // 8192

#define SCAN_NCTA 128
#define SCAN_TPB  256
#define HP 132           // hsh row pad (floats)
#define WS 516           // Wsh row stride (floats): conflict-free per-octet LDS.128

// SMEM: Wsh 64*516 | hsh 8*132 | part 8*64*9 | csh 128   (~152 KB)
#define SCAN_SMEM_FLOATS (64 * WS + 8 * HP + 8 * 64 * 9 + 128)
#define SCAN_SMEM_BYTES  (SCAN_SMEM_FLOATS * 4)

typedef unsigned long long ull;

#define FMA2(acc, a, b) \
    asm("fma.rn.f32x2 %0, %1, %2, %0;" : "+l"(acc) : "l"(a), "l"(b))
#define DUP2(d, s) \
    asm("mov.b64 %0, {%1, %1};" : "=l"(d) : "f"(s))
#define UNPK2(lo, hi, v) \
    asm("mov.b64 {%0, %1}, %2;" : "=f"(lo), "=f"(hi) : "l"(v))

__device__ __forceinline__ float fsigmoid(float x) {
    return __fdividef(1.f, 1.f + __expf(-x));
}
__device__ __forceinline__ float ftanh(float x) {
    float e = __expf(2.f * x);              // inf for large x -> 1; 0 for -inf -> -1
    return 1.f - __fdividef(2.f, e + 1.f);
}

// ---------------- device scratch (static, no allocation) ----------------
__device__ float g_gx[M_TOT * Gq];       // 64MB gate pre-activations; reused as probs
__device__ float g_io0[M_TOT * Hq];      // 16MB layer ping
__device__ float g_io1[M_TOT * Hq];      // 16MB layer pong
__device__ float g_h[2][Bq * Hq];        // recurrent h double buffer, [b][k]
__device__ unsigned g_flags[2][SCAN_NCTA * 32];  // per-CTA 128B-padded flags

// ---------------- input GEMM (double-buffered SMEM) ----------------------
__global__ void __launch_bounds__(256, 2) gemm_kernel(
    const float* __restrict__ A, const float* __restrict__ W,
    const float* __restrict__ bih, const float* __restrict__ bhh,
    float* __restrict__ C, int K)
{
    __shared__ float As[2][8][128];
    __shared__ float Bs[2][8][128];
    const int tid = threadIdx.x;
    const int m0 = blockIdx.y * 128;
    const int n0 = blockIdx.x * 128;
    const int lr = tid >> 1;
    const int lk = (tid & 1) * 4;
    const int tx = tid & 15;
    const int ty = tid >> 4;

    ull acc2[8][4];
#pragma unroll
    for (int i = 0; i < 8; ++i)
#pragma unroll
        for (int j = 0; j < 4; ++j) acc2[i][j] = 0ull;

    const float* Ap = A + (size_t)(m0 + lr) * K + lk;
    const float* Wp = W + (size_t)(n0 + lr) * K + lk;
    float4 pa = *reinterpret_cast<const float4*>(Ap);
    float4 pb = *reinterpret_cast<const float4*>(Wp);

    As[0][lk + 0][lr] = pa.x; As[0][lk + 1][lr] = pa.y;
    As[0][lk + 2][lr] = pa.z; As[0][lk + 3][lr] = pa.w;
    Bs[0][lk + 0][lr] = pb.x; Bs[0][lk + 1][lr] = pb.y;
    Bs[0][lk + 2][lr] = pb.z; Bs[0][lk + 3][lr] = pb.w;
    __syncthreads();

    const int nk = K >> 3;
    for (int kt = 0; kt < nk; ++kt) {
        const int buf = kt & 1;
        if (kt + 1 < nk) {
            pa = *reinterpret_cast<const float4*>(Ap + (kt + 1) * 8);
            pb = *reinterpret_cast<const float4*>(Wp + (kt + 1) * 8);
        }
#pragma unroll
        for (int kk = 0; kk < 8; ++kk) {
            float4 a0 = *reinterpret_cast<const float4*>(&As[buf][kk][ty * 4]);
            float4 a1 = *reinterpret_cast<const float4*>(&As[buf][kk][64 + ty * 4]);
            ulonglong2 bb0 = *reinterpret_cast<const ulonglong2*>(&Bs[buf][kk][tx * 4]);
            ulonglong2 bb1 = *reinterpret_cast<const ulonglong2*>(&Bs[buf][kk][64 + tx * 4]);
            float am[8] = {a0.x, a0.y, a0.z, a0.w, a1.x, a1.y, a1.z, a1.w};
            ull bp0 = bb0.x, bp1 = bb0.y, bp2 = bb1.x, bp3 = bb1.y;
#pragma unroll
            for (int i = 0; i < 8; ++i) {
                ull a2; DUP2(a2, am[i]);
                FMA2(acc2[i][0], a2, bp0);
                FMA2(acc2[i][1], a2, bp1);
                FMA2(acc2[i][2], a2, bp2);
                FMA2(acc2[i][3], a2, bp3);
            }
        }
        if (kt + 1 < nk) {
            const int nb = buf ^ 1;
            As[nb][lk + 0][lr] = pa.x; As[nb][lk + 1][lr] = pa.y;
            As[nb][lk + 2][lr] = pa.z; As[nb][lk + 3][lr] = pa.w;
            Bs[nb][lk + 0][lr] = pb.x; Bs[nb][lk + 1][lr] = pb.y;
            Bs[nb][lk + 2][lr] = pb.z; Bs[nb][lk + 3][lr] = pb.w;
            __syncthreads();
        }
    }

    float acc[8][8];
#pragma unroll
    for (int i = 0; i < 8; ++i)
#pragma unroll
        for (int j = 0; j < 4; ++j)
            UNPK2(acc[i][2 * j], acc[i][2 * j + 1], acc2[i][j]);

    const int nc0 = n0 + tx * 4;
    const int nc1 = n0 + 64 + tx * 4;
    float bs0[4], bs1[4];
#pragma unroll
    for (int j = 0; j < 4; ++j) {
        bs0[j] = bih[nc0 + j] + bhh[nc0 + j];
        bs1[j] = bih[nc1 + j] + bhh[nc1 + j];
    }
#pragma unroll
    for (int i = 0; i < 8; ++i) {
        int m = m0 + ((i < 4) ? (ty * 4 + i) : (64 + ty * 4 + i - 4));
        float4 v0, v1;
        v0.x = acc[i][0] + bs0[0]; v0.y = acc[i][1] + bs0[1];
        v0.z = acc[i][2] + bs0[2]; v0.w = acc[i][3] + bs0[3];
        v1.x = acc[i][4] + bs1[0]; v1.y = acc[i][5] + bs1[1];
        v1.z = acc[i][6] + bs1[2]; v1.w = acc[i][7] + bs1[3];
        *reinterpret_cast<float4*>(C + (size_t)m * Gq + nc0) = v0;
        *reinterpret_cast<float4*>(C + (size_t)m * Gq + nc1) = v1;
    }
}

// ---------------- persistent recurrent scan: 4 groups x 32 CTAs ----------
// CTA owns 16 h-cols (64 gate rows, W in SMEM). Dot: lane owns rows
// (lane, lane+32) over the warp's 64-k chunk; h via warp-broadcast LDS.
__global__ void __launch_bounds__(SCAN_TPB) lstm_scan_kernel(
    const float* __restrict__ gx,   // [b][s][2048]
    const float* __restrict__ Whh,  // [2048][512] this layer
    float* __restrict__ out,        // [b][s][512]
    unsigned ebase)                 // layer * Sq
{
    extern __shared__ float sm[];
    float* Wsh  = sm;                      // 64 * WS
    float* hsh  = Wsh + 64 * WS;           // 8 * HP
    float* part = hsh + 8 * HP;            // 8 * 64 * 9
    float* csh  = part + 8 * 64 * 9;       // 128

    const int tid   = threadIdx.x;
    const int cta   = blockIdx.x;
    const int group = cta >> 5;
    const int cidx  = cta & 31;
    const int j0    = cidx * 16;
    const int b0    = group * 8;
    const int wid   = tid >> 5;
    const int lane  = tid & 31;

    if (tid == 0) {
        g_flags[0][cta * 32] = 0u;
        g_flags[1][cta * 32] = 0u;
    }

    // load 64 Whh rows (stride WS): local rl -> global (rl>>4)*512 + j0 + (rl&15)
    for (int i = tid; i < 64 * 128; i += SCAN_TPB) {
        int rl = i >> 7;
        int k4 = i & 127;
        int grow = (rl >> 4) * Hq + j0 + (rl & 15);
        *reinterpret_cast<float4*>(Wsh + rl * WS + k4 * 4) =
            *reinterpret_cast<const float4*>(Whh + (size_t)grow * Hq + k4 * 4);
    }
    if (tid < 128) csh[tid] = 0.f;
    __syncthreads();

    const int bl = tid >> 4;           // gate-thread local batch (tid<128)
    const int jj = tid & 15;           // gate-thread h-col

    float gxv0 = 0.f, gxv1 = 0.f, gxv2 = 0.f, gxv3 = 0.f;
    if (tid < 128) {
        const float* gp = gx + (size_t)(b0 + bl) * Sq * Gq + j0 + jj;
        gxv0 = gp[0]; gxv1 = gp[Hq]; gxv2 = gp[2 * Hq]; gxv3 = gp[3 * Hq];
    }

    const float* Ws0 = Wsh + lane * WS;
    const float* Ws1 = Wsh + (lane + 32) * WS;
    const int kw = wid * 64;

    for (int t = 0; t < Sq; ++t) {
        const int cur = t & 1, nxt = cur ^ 1;

        if (t > 0) {
            // ---- wait: this group's 32 CTAs published h_t ----
            if (wid == 7) {
                unsigned target = ebase + (unsigned)t;
                const unsigned* f = &g_flags[cur][(group * 32 + lane) * 32];
                unsigned seen = 0u;
                do {
                    if (!seen) {
                        unsigned v;
                        asm volatile("ld.relaxed.gpu.global.u32 %0, [%1];"
                                     : "=r"(v) : "l"(f));
                        seen = (v == target) ? 1u : 0u;
                    }
                } while (__all_sync(0xffffffffu, seen) == 0);
            }
            __syncthreads();

            // ---- stage h_t (8 b x 512 k, L2-direct, coalesced) ----
            {
                const float4* hsrc =
                    reinterpret_cast<const float4*>(g_h[cur] + (size_t)b0 * Hq);
                int q = tid;
#pragma unroll
                for (int i = 0; i < 4; ++i, q += SCAN_TPB) {
                    int bb = q >> 7;
                    int kq = q & 127;
                    float4 v = __ldcg(hsrc + q);
                    *reinterpret_cast<float4*>(hsh + bb * HP + kq * 4) = v;
                }
            }
            __syncthreads();

            // ---- dot: warp wid -> k chunk [kw,kw+64); lane rows (lane,lane+32)
            {
                ull acc[2][8];
#pragma unroll
                for (int r = 0; r < 2; ++r)
#pragma unroll
                    for (int b = 0; b < 8; ++b) acc[r][b] = 0ull;
#pragma unroll
                for (int k4 = 0; k4 < 16; ++k4) {
                    int k = kw + k4 * 4;
                    ulonglong2 w0 = *reinterpret_cast<const ulonglong2*>(Ws0 + k);
                    ulonglong2 w1 = *reinterpret_cast<const ulonglong2*>(Ws1 + k);
#pragma unroll
                    for (int b = 0; b < 8; ++b) {
                        ulonglong2 hp =
                            *reinterpret_cast<const ulonglong2*>(hsh + b * HP + k);
                        FMA2(acc[0][b], hp.x, w0.x);
                        FMA2(acc[0][b], hp.y, w0.y);
                        FMA2(acc[1][b], hp.x, w1.x);
                        FMA2(acc[1][b], hp.y, w1.y);
                    }
                }
#pragma unroll
                for (int r = 0; r < 2; ++r)
#pragma unroll
                    for (int b = 0; b < 8; ++b) {
                        float lo, hi; UNPK2(lo, hi, acc[r][b]);
                        part[(wid * 64 + lane + r * 32) * 9 + b] = lo + hi;
                    }
            }
            __syncthreads();
        }

        // ---- gates (threads 0..127), early publish ----
        if (tid < 128) {
            float s0 = 0.f, s1 = 0.f, s2 = 0.f, s3 = 0.f;
            if (t > 0) {
#pragma unroll
                for (int w = 0; w < 8; ++w) {
                    s0 += part[(w * 64 +      jj) * 9 + bl];
                    s1 += part[(w * 64 + 16 + jj) * 9 + bl];
                    s2 += part[(w * 64 + 32 + jj) * 9 + bl];
                    s3 += part[(w * 64 + 48 + jj) * 9 + bl];
                }
            }
            float si = fsigmoid(s0 + gxv0);
            float sf = fsigmoid(s1 + gxv1);
            float tg = ftanh(s2 + gxv2);
            float so = fsigmoid(s3 + gxv3);
            float c  = sf * csh[tid] + si * tg;
            csh[tid] = c;
            float hn = so * ftanh(c);
            int bglob = b0 + bl;
            g_h[nxt][(size_t)bglob * Hq + j0 + jj] = hn;

            asm volatile("bar.sync 1, 128;" ::: "memory");   // gate warps only
            if (tid == 0) {
                unsigned val = ebase + (unsigned)(t + 1);
                asm volatile("membar.gl;" ::: "memory");
                asm volatile("st.release.gpu.global.u32 [%0], %1;"
                             :: "l"(&g_flags[nxt][cta * 32]), "r"(val) : "memory");
            }

            // off critical path: out store + next gx prefetch
            out[((size_t)bglob * Sq + t) * Hq + j0 + jj] = hn;
            int tn = (t + 1 < Sq) ? t + 1 : t;
            const float* gp = gx + ((size_t)bglob * Sq + tn) * Gq + j0 + jj;
            gxv0 = gp[0]; gxv1 = gp[Hq]; gxv2 = gp[2 * Hq]; gxv3 = gp[3 * Hq];
        }
        // no trailing __syncthreads: next step's post-poll sync orders hsh reuse
    }
}

// ---------------- softmax over sequence axis (per (b,h) column) ---------
__global__ void __launch_bounds__(256) softmax_kernel(
    const float* __restrict__ in, float* __restrict__ probs)
{
    int gw = (blockIdx.x * 256 + threadIdx.x) >> 5;
    int lane = threadIdx.x & 31;
    int bb = gw >> 9;
    int hh = gw & 511;
    const float* p = in + (size_t)bb * Sq * Hq + hh;
    float v[8];
    float mx = -3.4e38f;
#pragma unroll
    for (int i = 0; i < 8; ++i) {
        v[i] = p[(size_t)(lane + 32 * i) * Hq];
        mx = fmaxf(mx, v[i]);
    }
#pragma unroll
    for (int o = 16; o; o >>= 1) mx = fmaxf(mx, __shfl_xor_sync(0xffffffffu, mx, o));
    float sum = 0.f;
#pragma unroll
    for (int i = 0; i < 8; ++i) { v[i] = __expf(v[i] - mx); sum += v[i]; }
#pragma unroll
    for (int o = 16; o; o >>= 1) sum += __shfl_xor_sync(0xffffffffu, sum, o);
    float inv = 1.f / sum;
    float* q = probs + (size_t)bb * Sq * Hq + hh;
#pragma unroll
    for (int i = 0; i < 8; ++i) q[(size_t)(lane + 32 * i) * Hq] = v[i] * inv;
}

// ---------------- final FC ------------------------------------------------
__global__ void __launch_bounds__(256) fc_kernel(
    const float* __restrict__ probs, const float* __restrict__ Wfc,
    const float* __restrict__ bfc, float* __restrict__ out)
{
    int gw = (blockIdx.x * 256 + threadIdx.x) >> 5;
    int lane = threadIdx.x & 31;
    const float* p = probs + (size_t)gw * Hq;
    float a0 = 0.f, a1 = 0.f, a2 = 0.f, a3 = 0.f;
    for (int k = lane; k < Hq; k += 32) {
        float pv = p[k];
        a0 += pv * Wfc[k];
        a1 += pv * Wfc[Hq + k];
        a2 += pv * Wfc[2 * Hq + k];
        a3 += pv * Wfc[3 * Hq + k];
    }
#pragma unroll
    for (int o = 16; o; o >>= 1) {
        a0 += __shfl_xor_sync(0xffffffffu, a0, o);
        a1 += __shfl_xor_sync(0xffffffffu, a1, o);
        a2 += __shfl_xor_sync(0xffffffffu, a2, o);
        a3 += __shfl_xor_sync(0xffffffffu, a3, o);
    }
    if (lane == 0) {
        float4 r;
        r.x = a0 + bfc[0]; r.y = a1 + bfc[1];
        r.z = a2 + bfc[2]; r.w = a3 + bfc[3];
        *reinterpret_cast<float4*>(out + (size_t)gw * 4) = r;
    }
}

// ---------------- launcher -----------------------------------------------
extern "C" void kernel_launch(void* const* d_in, const int* in_sizes, int n_in,
                              void* d_out, int out_size)
{
    const float* x    = (const float*)d_in[0];
    const float* Wih0 = (const float*)d_in[1];
    const float* WihR = (const float*)d_in[2];
    const float* Whh  = (const float*)d_in[3];
    const float* bih  = (const float*)d_in[4];
    const float* bhh  = (const float*)d_in[5];
    const float* Wfc  = (const float*)d_in[6];
    const float* bfc  = (const float*)d_in[7];
    float* out = (float*)d_out;

    float *gx, *io0, *io1;
    cudaGetSymbolAddress((void**)&gx,  g_gx);
    cudaGetSymbolAddress((void**)&io0, g_io0);
    cudaGetSymbolAddress((void**)&io1, g_io1);

    cudaFuncSetAttribute(lstm_scan_kernel,
                         cudaFuncAttributeMaxDynamicSharedMemorySize,
                         SCAN_SMEM_BYTES);

    const float* lin[4]  = {x, io0, io1, io0};
    float*       lout[4] = {io0, io1, io0, io1};

    for (int l = 0; l < 4; ++l) {
        int K = (l == 0) ? Eq : Hq;
        const float* Wih = (l == 0) ? Wih0 : (WihR + (size_t)(l - 1) * Gq * Hq);
        gemm_kernel<<<dim3(Gq / 128, M_TOT / 128), 256>>>(
            lin[l], Wih, bih + (size_t)l * Gq, bhh + (size_t)l * Gq, gx, K);
        lstm_scan_kernel<<<SCAN_NCTA, SCAN_TPB, SCAN_SMEM_BYTES>>>(
            gx, Whh + (size_t)l * Gq * Hq, lout[l], (unsigned)(l * Sq));
    }

    softmax_kernel<<<2048, 256>>>(io1, gx);
    fc_kernel<<<1024, 256>>>(gx, Wfc, bfc, out);
}